// round 12
// baseline (speedup 1.0000x reference)
#include <cuda_runtime.h>
#include <cuda_fp16.h>
#include <stdint.h>

#define NROWS 8192
#define DM 14
#define MF 36
#define EPS 1e-5f
typedef unsigned long long u64;

__device__ __align__(16) float g_h[NROWS * DM];
__device__ __align__(16) float g_q[NROWS * DM];   // pre-scaled by D^-0.5*log2(e)
__device__ __align__(16) float g_part[8 * NROWS * 16];
__device__ __align__(16) __half g_kp[4 * NROWS * 8];   // [arr][key][8] f16
__device__ __align__(16) __half g_vt[32][NROWS];       // [dim-ish][key] f16
__device__ __align__(16) __half g_w1p[2 * 4 * 2048 * 8];  // per-layer W1 repack
__device__ __align__(16) __half g_w2p[2 * 32 * 2048];     // per-layer W2t repack
__device__ float g_sizef[NROWS];
__device__ float g_qn[NROWS];
__device__ float g_kmaxpart[128];

// ---- helpers ----
__device__ __forceinline__ u64 f2u(float2 v) { union { float2 f; u64 u; } c; c.f = v; return c.u; }
__device__ __forceinline__ float2 u2f(u64 u) { union { float2 f; u64 u; } c; c.u = u; return c.f; }
__device__ __forceinline__ u64 pack2(float lo, float hi) { float2 v; v.x = lo; v.y = hi; return f2u(v); }
__device__ __forceinline__ u64 fma2(u64 a, u64 b, u64 c) {
    u64 d; asm("fma.rn.f32x2 %0,%1,%2,%3;" : "=l"(d) : "l"(a), "l"(b), "l"(c)); return d;
}
__device__ __forceinline__ float ex2f(float x) {
    float y; asm("ex2.approx.f32 %0,%1;" : "=f"(y) : "f"(x)); return y;
}
__device__ __forceinline__ float wsum(float v) {
#pragma unroll
    for (int o = 16; o; o >>= 1) v += __shfl_xor_sync(0xffffffffu, v, o);
    return v;
}
__device__ __forceinline__ float wmax(float v) {
#pragma unroll
    for (int o = 16; o; o >>= 1) v = fmaxf(v, __shfl_xor_sync(0xffffffffu, v, o));
    return v;
}
__device__ __forceinline__ void cp16(uint32_t dst, const void* src) {
    asm volatile("cp.async.cg.shared.global [%0], [%1], 16;" :: "r"(dst), "l"(src));
}
#define CP_COMMIT() asm volatile("cp.async.commit_group;")
#define CP_WAIT(N)  asm volatile("cp.async.wait_group %0;" :: "n"(N))

__device__ __forceinline__ uint32_t h2pack(float a, float b) {
    __half2 h = __floats2half2_rn(a, b);
    return *(uint32_t*)&h;
}
__device__ __forceinline__ void mma16816(float* d, const uint32_t* a, const uint32_t* b, const float* c) {
    asm volatile(
        "mma.sync.aligned.m16n8k16.row.col.f32.f16.f16.f32 "
        "{%0,%1,%2,%3}, {%4,%5,%6,%7}, {%8,%9}, {%10,%11,%12,%13};"
        : "=f"(d[0]), "=f"(d[1]), "=f"(d[2]), "=f"(d[3])
        : "r"(a[0]), "r"(a[1]), "r"(a[2]), "r"(a[3]), "r"(b[0]), "r"(b[1]),
          "f"(c[0]), "f"(c[1]), "f"(c[2]), "f"(c[3]));
}

// ---------------- fused QKV projection + prep ----------------
#define QS 49
__global__ void __launch_bounds__(256, 1)
qkv_prep_kernel(const float* __restrict__ x0, int use_x,
                const float* __restrict__ W, const float* __restrict__ b) {
    __shared__ float Ws[42 * 14], bs[42], hs[64 * 14], qkvs[64 * QS], sp[2];
    const float* hin = use_x ? x0 : g_h;
    const int t = threadIdx.x;
    const int rb = blockIdx.x * 64;
    for (int i = t; i < 588; i += 256) Ws[i] = W[i];
    if (t < 42) bs[t] = b[t];
    for (int i = t; i < 64 * 14; i += 256) hs[i] = hin[rb * DM + i];
    __syncthreads();
    const float scale = rsqrtf(14.0f) * 1.44269504f;
    for (int idx = t; idx < 64 * 42; idx += 256) {
        int r = idx / 42, c = idx % 42;
        float s = bs[c];
#pragma unroll
        for (int d = 0; d < 14; d++) s = fmaf(hs[r * 14 + d], Ws[c * 14 + d], s);
        qkvs[r * QS + c] = (c < 14) ? s * scale : s;
    }
    __syncthreads();

    if (t < 64) {
        int row = rb + t;
        const float* qr = qkvs + t * QS;
        float qn = 0.f, kn = 0.f;
        float kv[14], vv[14];
#pragma unroll
        for (int d = 0; d < 14; d++) {
            float qf = qr[d];
            g_q[row * DM + d] = qf;
            qn = fmaf(qf, qf, qn);
            kv[d] = qr[14 + d]; kn = fmaf(kv[d], kv[d], kn);
            vv[d] = qr[28 + d];
        }
        g_qn[row] = sqrtf(qn);

        __half hi[16], lo[16];
#pragma unroll
        for (int d = 0; d < 14; d++) {
            hi[d] = __float2half_rn(kv[d]);
            lo[d] = __float2half_rn(kv[d] - __half2float(hi[d]));
        }
        hi[14] = __float2half_rn(1.0f); hi[15] = __float2half_rn(0.f);
        lo[14] = __float2half_rn(0.f);  lo[15] = __float2half_rn(0.f);
        {
            __half* p0 = g_kp + (0 * NROWS + row) * 8;
            __half* p1 = g_kp + (1 * NROWS + row) * 8;
            __half* p2 = g_kp + (2 * NROWS + row) * 8;
            __half* p3 = g_kp + (3 * NROWS + row) * 8;
#pragma unroll
            for (int d = 0; d < 8; d++) { p0[d] = hi[d]; p1[d] = hi[8 + d]; p2[d] = lo[d]; p3[d] = lo[8 + d]; }
        }
#pragma unroll
        for (int d = 0; d < 14; d++) {
            __half vh = __float2half_rn(vv[d]);
            g_vt[d][row] = vh;
            g_vt[16 + d][row] = __float2half_rn(vv[d] - __half2float(vh));
        }
        g_vt[14][row] = __float2half_rn(1.0f);
        g_vt[15][row] = __float2half_rn(0.f);
        g_vt[30][row] = __float2half_rn(0.f);
        g_vt[31][row] = __float2half_rn(0.f);

        kn = wmax(kn);
        if ((t & 31) == 0) sp[t >> 5] = kn;
    }
    __syncthreads();
    if (t == 0) g_kmaxpart[blockIdx.x] = fmaxf(sp[0], sp[1]);
}

// ---------------- mma.sync flash attention, 8-way key split ----------------
#define KBUF 16384
#define BUFSTRIDE (16384 + 16896)
#define ATTN_SMEM (2 * BUFSTRIDE)
__device__ __forceinline__ void tile_cp2(uint32_t sbase, int buf, int key0c, int t) {
    uint32_t dst = sbase + (uint32_t)buf * BUFSTRIDE;
#pragma unroll
    for (int s = 0; s < 4; s++) {
        int i = t + s * 256;
        int a = i >> 8, key = i & 255;
        cp16(dst + (uint32_t)a * 4096 + (uint32_t)key * 16,
             g_kp + ((size_t)a * NROWS + key0c + key) * 8);
    }
#pragma unroll
    for (int s = 0; s < 4; s++) {
        int i = t + s * 256;
        int row = i >> 5, seg = i & 31;
        cp16(dst + KBUF + (uint32_t)row * 528 + (uint32_t)seg * 16,
             &g_vt[row][key0c + seg * 8]);
    }
}

__global__ void __launch_bounds__(256, 3)
attn_mma_kernel() {
    extern __shared__ char smc[];
    const int t = threadIdx.x, lane = t & 31, warp = t >> 5;
    const int g = lane >> 2, tg = lane & 3;
    const int tile = blockIdx.x >> 3, part = blockIdx.x & 7;
    const int key0 = part * 1024;
    const uint32_t sbase = (uint32_t)__cvta_generic_to_shared(smc);

    float mk2 = 0.f;
    for (int i = lane; i < 128; i += 32) mk2 = fmaxf(mk2, __ldg(g_kmaxpart + i));
    mk2 = wmax(mk2);
    const float maxk = sqrtf(mk2);

    const int qbase = tile * 128 + warp * 16;
    uint32_t qhi[4], qlo[4];
    {
        int r0 = qbase + g, r1 = r0 + 8;
        float v0a = g_q[r0 * DM + 2 * tg],     v1a = g_q[r0 * DM + 2 * tg + 1];
        float v0b = g_q[r1 * DM + 2 * tg],     v1b = g_q[r1 * DM + 2 * tg + 1];
        float v2a, v3a, v2b, v3b;
        if (tg < 3) {
            v2a = g_q[r0 * DM + 8 + 2 * tg]; v3a = g_q[r0 * DM + 9 + 2 * tg];
            v2b = g_q[r1 * DM + 8 + 2 * tg]; v3b = g_q[r1 * DM + 9 + 2 * tg];
        } else {
            v2a = -__ldg(g_qn + r0) * maxk; v3a = 0.f;
            v2b = -__ldg(g_qn + r1) * maxk; v3b = 0.f;
        }
        float vals[4][2] = {{v0a, v1a}, {v0b, v1b}, {v2a, v3a}, {v2b, v3b}};
#pragma unroll
        for (int i = 0; i < 4; i++) {
            qhi[i] = h2pack(vals[i][0], vals[i][1]);
            __half2 hh = *(__half2*)&qhi[i];
            qlo[i] = h2pack(vals[i][0] - __low2float(hh), vals[i][1] - __high2float(hh));
        }
    }

    float O0[4] = {0.f, 0.f, 0.f, 0.f};
    float O1[4] = {0.f, 0.f, 0.f, 0.f};

    tile_cp2(sbase, 0, key0, t);
    CP_COMMIT();

    for (int c = 0; c < 4; c++) {
        if (c < 3) {
            tile_cp2(sbase, (c + 1) & 1, key0 + (c + 1) * 256, t);
            CP_COMMIT();
            CP_WAIT(1);
        } else {
            CP_WAIT(0);
        }
        __syncthreads();

        const char* kb = smc + (c & 1) * BUFSTRIDE;
        const char* vb = kb + KBUF;

        for (int j = 0; j < 256; j += 16) {
            const char* k0 = kb + (size_t)(j + g) * 16 + tg * 4;
            const char* k1 = kb + (size_t)(j + 8 + g) * 16 + tg * 4;
            uint32_t bh0[2] = { *(const uint32_t*)k0,          *(const uint32_t*)(k0 + 4096) };
            uint32_t bl0[2] = { *(const uint32_t*)(k0 + 8192), *(const uint32_t*)(k0 + 12288) };
            uint32_t bh1[2] = { *(const uint32_t*)k1,          *(const uint32_t*)(k1 + 4096) };
            uint32_t bl1[2] = { *(const uint32_t*)(k1 + 8192), *(const uint32_t*)(k1 + 12288) };

            float S0[4] = {0.f, 0.f, 0.f, 0.f}, S1[4] = {0.f, 0.f, 0.f, 0.f};
            mma16816(S0, qhi, bh0, S0);
            mma16816(S0, qhi, bl0, S0);
            mma16816(S0, qlo, bh0, S0);
            mma16816(S1, qhi, bh1, S1);
            mma16816(S1, qhi, bl1, S1);
            mma16816(S1, qlo, bh1, S1);

            float p[8];
#pragma unroll
            for (int i = 0; i < 4; i++) { p[i] = ex2f(S0[i]); p[4 + i] = ex2f(S1[i]); }
            uint32_t phi[4], plo[4];
#pragma unroll
            for (int i = 0; i < 4; i++) {
                phi[i] = h2pack(p[2 * i], p[2 * i + 1]);
                __half2 hh = *(__half2*)&phi[i];
                plo[i] = h2pack(p[2 * i] - __low2float(hh), p[2 * i + 1] - __high2float(hh));
            }

            const char* v0 = vb + (size_t)(j * 2 + tg * 4);
            uint32_t vh0[2] = { *(const uint32_t*)(v0 + (size_t)g * 528),
                                *(const uint32_t*)(v0 + (size_t)g * 528 + 16) };
            uint32_t vh1[2] = { *(const uint32_t*)(v0 + (size_t)(8 + g) * 528),
                                *(const uint32_t*)(v0 + (size_t)(8 + g) * 528 + 16) };
            uint32_t vl0[2] = { *(const uint32_t*)(v0 + (size_t)(16 + g) * 528),
                                *(const uint32_t*)(v0 + (size_t)(16 + g) * 528 + 16) };
            uint32_t vl1[2] = { *(const uint32_t*)(v0 + (size_t)(24 + g) * 528),
                                *(const uint32_t*)(v0 + (size_t)(24 + g) * 528 + 16) };

            mma16816(O0, phi, vh0, O0);
            mma16816(O1, phi, vh1, O1);
            mma16816(O0, plo, vh0, O0);
            mma16816(O1, plo, vh1, O1);
            mma16816(O0, phi, vl0, O0);
            mma16816(O1, phi, vl1, O1);
        }
        __syncthreads();
    }

    {
        int r0 = qbase + g;
        float* d0 = g_part + ((size_t)part * NROWS + r0) * 16;
        float* d1 = g_part + ((size_t)part * NROWS + r0 + 8) * 16;
        *(float2*)(d0 + 2 * tg)     = make_float2(O0[0], O0[1]);
        *(float2*)(d0 + 8 + 2 * tg) = make_float2(O1[0], O1[1]);
        *(float2*)(d1 + 2 * tg)     = make_float2(O0[2], O0[3]);
        *(float2*)(d1 + 8 + 2 * tg) = make_float2(O1[2], O1[3]);
    }
}

// ---------------- wprep (both layers, once) ----------------
__global__ void __launch_bounds__(256, 1)
wprep_all_kernel(const float* __restrict__ W1a, const float* __restrict__ b1a,
                 const float* __restrict__ W2a) {
    int idx = blockIdx.x * 256 + threadIdx.x;
    int layer = idx >> 11, j = idx & 2047;
    const float* W1 = W1a + layer * 28672;
    const float* b1 = b1a + layer * 2048;
    const float* W2 = W2a + layer * 28672;
    __half* w1p = g_w1p + layer * 65536;
    __half* w2p = g_w2p + layer * 65536;

    __half hi[16], lo[16];
#pragma unroll
    for (int d = 0; d < 14; d++) {
        float w = W1[j * 14 + d];
        hi[d] = __float2half_rn(w);
        lo[d] = __float2half_rn(w - __half2float(hi[d]));
    }
    {
        float bb = __ldg(b1 + j);
        hi[14] = __float2half_rn(bb);
        lo[14] = __float2half_rn(bb - __half2float(hi[14]));
        hi[15] = __float2half_rn(0.f); lo[15] = __float2half_rn(0.f);
    }
    {
        __half* p0 = w1p + (0 * 2048 + j) * 8;
        __half* p1 = w1p + (1 * 2048 + j) * 8;
        __half* p2 = w1p + (2 * 2048 + j) * 8;
        __half* p3 = w1p + (3 * 2048 + j) * 8;
#pragma unroll
        for (int d = 0; d < 8; d++) { p0[d] = hi[d]; p1[d] = hi[8 + d]; p2[d] = lo[d]; p3[d] = lo[8 + d]; }
    }
#pragma unroll
    for (int d = 0; d < 14; d++) {
        float w = W2[d * 2048 + j];
        __half wh = __float2half_rn(w);
        w2p[d * 2048 + j] = wh;
        w2p[(16 + d) * 2048 + j] = __float2half_rn(w - __half2float(wh));
    }
    w2p[14 * 2048 + j] = __float2half_rn(0.f);
    w2p[15 * 2048 + j] = __float2half_rn(0.f);
    w2p[30 * 2048 + j] = __float2half_rn(0.f);
    w2p[31 * 2048 + j] = __float2half_rn(0.f);
}

// ---------------- fused combine + FFN + LN2 (+head1 on layer 1) ----------------
#define FW1B 16384
#define FBUF (FW1B + 16896)
#define FFN_SMEM (2 * FBUF)
__device__ __forceinline__ void ffn_cp(uint32_t sbase, int buf, int chunk, int t, int layer) {
    uint32_t dst = sbase + (uint32_t)buf * FBUF;
    const __half* w1p = g_w1p + layer * 65536;
    const __half* w2p = g_w2p + layer * 65536;
#pragma unroll
    for (int s = 0; s < 4; s++) {
        int i = t + s * 256;
        int a = i >> 8, j = i & 255;
        cp16(dst + (uint32_t)a * 4096 + (uint32_t)j * 16,
             w1p + ((size_t)a * 2048 + chunk * 256 + j) * 8);
    }
#pragma unroll
    for (int s = 0; s < 4; s++) {
        int i = t + s * 256;
        int row = i >> 5, seg = i & 31;
        cp16(dst + FW1B + (uint32_t)row * 528 + (uint32_t)seg * 16,
             w2p + (size_t)row * 2048 + chunk * 256 + seg * 8);
    }
}

__global__ void __launch_bounds__(256, 2)
ffn_mma_kernel(int layer, const float* __restrict__ x0, int use_x,
               const float* __restrict__ Wo, const float* __restrict__ bo,
               const float* __restrict__ ln1g, const float* __restrict__ ln1b,
               const float* __restrict__ b2,
               const float* __restrict__ lng, const float* __restrict__ lnb,
               const float* __restrict__ fc1w, const float* __restrict__ fc1b,
               const float* __restrict__ fc2w, const float* __restrict__ fc2b,
               float* __restrict__ out) {
    extern __shared__ char smc[];
    __shared__ float wos[196], bos[14], hbuf[32 * 14];
    const int t = threadIdx.x, lane = t & 31, warp = t >> 5;
    const int g = lane >> 2, tg = lane & 3;
    const int rw = warp & 1, jq = warp >> 1;
    const uint32_t sbase = (uint32_t)__cvta_generic_to_shared(smc);
    const int rbase0 = blockIdx.x * 32;

    // ---- prefetch first two weight chunks BEFORE the latency-bound prologue ----
    ffn_cp(sbase, 0, 0, t, layer);
    CP_COMMIT();
    ffn_cp(sbase, 1, 1, t, layer);
    CP_COMMIT();

    // ---- combine prologue: merge 8 attention partials -> out-proj -> +res -> LN1 ----
    for (int i = t; i < 196; i += 256) wos[i] = Wo[i];
    if (t < 14) bos[t] = bo[t];
    __syncthreads();
    {
        const float* hin = use_x ? x0 : g_h;
        const int lrow = t >> 3;
        const int row = rbase0 + lrow;
        const int e = lane & 7;
        float2 acc = make_float2(0.f, 0.f);
#pragma unroll
        for (int p = 0; p < 8; p++) {
            float2 v = ((const float2*)(g_part + ((size_t)p * NROWS + row) * 16))[e];
            acc.x += v.x; acc.y += v.y;
        }
        float l = __shfl_sync(0xffffffffu, acc.x, lane | 7);
        float inv = 1.f / l;
        float ax = acc.x * inv, ay = acc.y * inv;
        float a[14];
        const int base = lane & 24;
#pragma unroll
        for (int dp = 0; dp < 7; dp++) {
            a[2 * dp]     = __shfl_sync(0xffffffffu, ax, base + dp);
            a[2 * dp + 1] = __shfl_sync(0xffffffffu, ay, base + dp);
        }
        float pre0 = 0.f, pre1 = 0.f;
        if (e < 7) {
            int d2 = 2 * e;
            pre0 = bos[d2]; pre1 = bos[d2 + 1];
#pragma unroll
            for (int d = 0; d < 14; d++) {
                pre0 = fmaf(a[d], wos[d2 * 14 + d], pre0);
                pre1 = fmaf(a[d], wos[(d2 + 1) * 14 + d], pre1);
            }
            pre0 += hin[row * DM + d2];
            pre1 += hin[row * DM + d2 + 1];
        }
        float s = pre0 + pre1;
#pragma unroll
        for (int o = 4; o; o >>= 1) s += __shfl_xor_sync(0xffffffffu, s, o);
        float mu = s * (1.f / 14.f);
        float z0 = (e < 7) ? pre0 - mu : 0.f;
        float z1 = (e < 7) ? pre1 - mu : 0.f;
        float v = z0 * z0 + z1 * z1;
#pragma unroll
        for (int o = 4; o; o >>= 1) v += __shfl_xor_sync(0xffffffffu, v, o);
        float rs = rsqrtf(v * (1.f / 14.f) + EPS);
        if (e < 7) {
            int d2 = 2 * e;
            hbuf[lrow * 14 + d2]     = z0 * rs * __ldg(ln1g + d2)     + __ldg(ln1b + d2);
            hbuf[lrow * 14 + d2 + 1] = z1 * rs * __ldg(ln1g + d2 + 1) + __ldg(ln1b + d2 + 1);
        }
    }
    __syncthreads();

    // ---- h fragments from smem (hi/lo), col14 = 1.0 pairs with b1 in W1 col14 ----
    uint32_t qhi[4], qlo[4];
    {
        int lr0 = rw * 16 + g, lr1 = lr0 + 8;
        float v0a = hbuf[lr0 * 14 + 2 * tg],     v1a = hbuf[lr0 * 14 + 2 * tg + 1];
        float v0b = hbuf[lr1 * 14 + 2 * tg],     v1b = hbuf[lr1 * 14 + 2 * tg + 1];
        float v2a, v3a, v2b, v3b;
        if (tg < 3) {
            v2a = hbuf[lr0 * 14 + 8 + 2 * tg]; v3a = hbuf[lr0 * 14 + 9 + 2 * tg];
            v2b = hbuf[lr1 * 14 + 8 + 2 * tg]; v3b = hbuf[lr1 * 14 + 9 + 2 * tg];
        } else {
            v2a = 1.0f; v3a = 0.f;
            v2b = 1.0f; v3b = 0.f;
        }
        float vals[4][2] = {{v0a, v1a}, {v0b, v1b}, {v2a, v3a}, {v2b, v3b}};
#pragma unroll
        for (int i = 0; i < 4; i++) {
            qhi[i] = h2pack(vals[i][0], vals[i][1]);
            __half2 hh = *(__half2*)&qhi[i];
            qlo[i] = h2pack(vals[i][0] - __low2float(hh), vals[i][1] - __high2float(hh));
        }
    }

    float O0[4] = {0.f, 0.f, 0.f, 0.f};
    float O1[4] = {0.f, 0.f, 0.f, 0.f};

    for (int c = 0; c < 8; c++) {
        CP_WAIT(1);               // chunk c (buffer c&1) landed
        __syncthreads();

        const char* kb = smc + (c & 1) * FBUF;
        const char* vb = kb + FW1B;

        for (int step = 0; step < 4; step++) {
            const int j = jq * 64 + step * 16;
            const char* k0 = kb + (size_t)(j + g) * 16 + tg * 4;
            const char* k1 = kb + (size_t)(j + 8 + g) * 16 + tg * 4;
            uint32_t bh0[2] = { *(const uint32_t*)k0,          *(const uint32_t*)(k0 + 4096) };
            uint32_t bl0[2] = { *(const uint32_t*)(k0 + 8192), *(const uint32_t*)(k0 + 12288) };
            uint32_t bh1[2] = { *(const uint32_t*)k1,          *(const uint32_t*)(k1 + 4096) };
            uint32_t bl1[2] = { *(const uint32_t*)(k1 + 8192), *(const uint32_t*)(k1 + 12288) };

            float S0[4] = {0.f, 0.f, 0.f, 0.f}, S1[4] = {0.f, 0.f, 0.f, 0.f};
            mma16816(S0, qhi, bh0, S0);
            mma16816(S0, qhi, bl0, S0);
            mma16816(S0, qlo, bh0, S0);
            mma16816(S1, qhi, bh1, S1);
            mma16816(S1, qhi, bl1, S1);
            mma16816(S1, qlo, bh1, S1);

            float p[8];
#pragma unroll
            for (int i = 0; i < 4; i++) { p[i] = fmaxf(S0[i], 0.f); p[4 + i] = fmaxf(S1[i], 0.f); }
            uint32_t phi[4], plo[4];
#pragma unroll
            for (int i = 0; i < 4; i++) {
                phi[i] = h2pack(p[2 * i], p[2 * i + 1]);
                __half2 hh = *(__half2*)&phi[i];
                plo[i] = h2pack(p[2 * i] - __low2float(hh), p[2 * i + 1] - __high2float(hh));
            }

            const char* v0 = vb + (size_t)(j * 2 + tg * 4);
            uint32_t vh0[2] = { *(const uint32_t*)(v0 + (size_t)g * 528),
                                *(const uint32_t*)(v0 + (size_t)g * 528 + 16) };
            uint32_t vh1[2] = { *(const uint32_t*)(v0 + (size_t)(8 + g) * 528),
                                *(const uint32_t*)(v0 + (size_t)(8 + g) * 528 + 16) };
            uint32_t vl0[2] = { *(const uint32_t*)(v0 + (size_t)(16 + g) * 528),
                                *(const uint32_t*)(v0 + (size_t)(16 + g) * 528 + 16) };
            uint32_t vl1[2] = { *(const uint32_t*)(v0 + (size_t)(24 + g) * 528),
                                *(const uint32_t*)(v0 + (size_t)(24 + g) * 528 + 16) };

            mma16816(O0, phi, vh0, O0);
            mma16816(O1, phi, vh1, O1);
            mma16816(O0, plo, vh0, O0);
            mma16816(O1, plo, vh1, O1);
            mma16816(O0, phi, vl0, O0);
            mma16816(O1, phi, vl1, O1);
        }
        __syncthreads();          // all reads of buffer c&1 done
        if (c + 2 < 8) {
            ffn_cp(sbase, c & 1, c + 2, t, layer);
            CP_COMMIT();
        }
    }

    // ---- merge 4 jq groups (parallel slices, single sync), then LN2 epilogue ----
    {
        float* osum = (float*)smc;        // [grp][32][16] = 8KB, buffers dead
        int lr = rw * 16 + g;
        float* om = osum + jq * 512;
        om[lr * 16 + 2 * tg]           = O0[0];
        om[lr * 16 + 2 * tg + 1]       = O0[1];
        om[lr * 16 + 8 + 2 * tg]       = O1[0];
        om[lr * 16 + 9 + 2 * tg]       = O1[1];
        om[(lr + 8) * 16 + 2 * tg]     = O0[2];
        om[(lr + 8) * 16 + 2 * tg + 1] = O0[3];
        om[(lr + 8) * 16 + 8 + 2 * tg] = O1[2];
        om[(lr + 8) * 16 + 9 + 2 * tg] = O1[3];
        __syncthreads();
        if (t < 32) {
            int row = rbase0 + t;
            float pre[14], mu = 0.f;
#pragma unroll
            for (int d = 0; d < 14; d++) {
                float v = osum[t * 16 + d] + osum[512 + t * 16 + d]
                        + osum[1024 + t * 16 + d] + osum[1536 + t * 16 + d]
                        + __ldg(b2 + d) + hbuf[t * 14 + d];
                pre[d] = v; mu += v;
            }
            mu *= (1.f / 14.f);
            float var = 0.f;
#pragma unroll
            for (int d = 0; d < 14; d++) { float z = pre[d] - mu; var = fmaf(z, z, var); }
            float rs = rsqrtf(var * (1.f / 14.f) + EPS);
            float hv[14];
#pragma unroll
            for (int d = 0; d < 14; d++) {
                hv[d] = (pre[d] - mu) * rs * __ldg(lng + d) + __ldg(lnb + d);
                g_h[row * DM + d] = hv[d];
            }
            if (layer == 1) {
                float size = __ldg(fc2b);
#pragma unroll
                for (int d2 = 0; d2 < 14; d2++) {
                    float s = __ldg(fc1b + d2);
#pragma unroll
                    for (int d = 0; d < 14; d++) s = fmaf(hv[d], __ldg(fc1w + d2 * 14 + d), s);
                    size = fmaf(s, __ldg(fc2w + d2), size);
                }
                out[row] = size;
                g_sizef[row] = (float)(int)size;
            }
        }
    }
}

// ---------------- head 2: 32 rows/CTA ----------------
__global__ void __launch_bounds__(256, 1)
head2_kernel(const float* __restrict__ x, const float* __restrict__ y,
             const float* __restrict__ w3, const float* __restrict__ b3,
             const float* __restrict__ w4, const float* __restrict__ b4,
             const float* __restrict__ w5, const float* __restrict__ b5,
             float* __restrict__ out) {
    extern __shared__ float sm[];
    float* w3s = sm;             // 13056
    float* ins = w3s + 13056;    // 1632
    float* red = ins + 1632;     // 256
    float* r1f = red + 256;      // 8704
    float* w4s = r1f + 8704;     // 16640
    const int t = threadIdx.x, lane = t & 31, warp = t >> 5;
    const int rbase = blockIdx.x * 32;
    for (int i = t; i < 13056; i += 256) w3s[i] = w3[i];
    for (int i = t; i < 32 * 51; i += 256) {
        int r = i / 51, c = i % 51, row = rbase + r;
        float v;
        if (c == 0)      v = g_sizef[row];
        else if (c < 15) v = x[row * DM + c - 1];
        else             v = y[row * MF + c - 15];
        ins[i] = v;
    }
    __syncthreads();

    float r1a[32];
    float b3t = __ldg(b3 + t);
#pragma unroll
    for (int r = 0; r < 32; r++) r1a[r] = b3t;
    for (int i = 0; i < 51; i++) {
        float w = w3s[t * 51 + i];
#pragma unroll
        for (int r = 0; r < 32; r++) r1a[r] = fmaf(ins[r * 51 + i], w, r1a[r]);
    }
#pragma unroll
    for (int rp = 0; rp < 16; rp++) {
        float2 v;
        v.x = fmaxf(r1a[2 * rp], 0.f);
        v.y = fmaxf(r1a[2 * rp + 1], 0.f);
        ((float2*)r1f)[t * 17 + rp] = v;
    }
    __syncthreads();

    u64 r2a2[16];
    float b4t = __ldg(b4 + t);
#pragma unroll
    for (int rp = 0; rp < 16; rp++) r2a2[rp] = pack2(b4t, b4t);
    for (int c = 0; c < 4; c++) {
        for (int i = t; i < 256 * 64; i += 256) {
            int o = i >> 6, jj = i & 63;
            w4s[o * 65 + jj] = __ldg(w4 + o * 256 + c * 64 + jj);
        }
        __syncthreads();
#pragma unroll 2
        for (int jj = 0; jj < 64; jj++) {
            float w = w4s[t * 65 + jj];
            u64 w2p = pack2(w, w);
            const float2* rp1 = ((const float2*)r1f) + (c * 64 + jj) * 17;
#pragma unroll
            for (int rp = 0; rp < 16; rp++) r2a2[rp] = fma2(f2u(rp1[rp]), w2p, r2a2[rp]);
        }
        __syncthreads();
    }

    float w5t = __ldg(w5 + t);
#pragma unroll
    for (int rp = 0; rp < 16; rp++) {
        float2 f = u2f(r2a2[rp]);
        float v0 = wsum(fmaxf(f.x, 0.f) * w5t);
        float v1 = wsum(fmaxf(f.y, 0.f) * w5t);
        if (lane == 0) {
            red[warp * 32 + 2 * rp] = v0;
            red[warp * 32 + 2 * rp + 1] = v1;
        }
    }
    __syncthreads();
    if (t < 32) {
        float s = __ldg(b5);
        for (int w = 0; w < 8; w++) s += red[w * 32 + t];
        int row = rbase + t;
        out[NROWS + row] = (g_sizef[row] != 0.f) ? s : 0.f;
    }
}

// ---------------- launcher ----------------
extern "C" void kernel_launch(void* const* d_in, const int* in_sizes, int n_in,
                              void* d_out, int out_size) {
    const float* x    = (const float*)d_in[0];
    const float* y    = (const float*)d_in[1];
    const float* wqkv = (const float*)d_in[2];
    const float* bqkv = (const float*)d_in[3];
    const float* wo   = (const float*)d_in[4];
    const float* bo   = (const float*)d_in[5];
    const float* ln1g = (const float*)d_in[6];
    const float* ln1b = (const float*)d_in[7];
    const float* ffw1 = (const float*)d_in[8];
    const float* ffb1 = (const float*)d_in[9];
    const float* ffw2 = (const float*)d_in[10];
    const float* ffb2 = (const float*)d_in[11];
    const float* ln2g = (const float*)d_in[12];
    const float* ln2b = (const float*)d_in[13];
    const float* fc1w = (const float*)d_in[14];
    const float* fc1b = (const float*)d_in[15];
    const float* fc2w = (const float*)d_in[16];
    const float* fc2b = (const float*)d_in[17];
    const float* fc3w = (const float*)d_in[18];
    const float* fc3b = (const float*)d_in[19];
    const float* fc4w = (const float*)d_in[20];
    const float* fc4b = (const float*)d_in[21];
    const float* fc5w = (const float*)d_in[22];
    const float* fc5b = (const float*)d_in[23];
    float* out = (float*)d_out;

    const int h2_smem = (13056 + 1632 + 256 + 8704 + 16640) * (int)sizeof(float);
    cudaFuncSetAttribute(attn_mma_kernel, cudaFuncAttributeMaxDynamicSharedMemorySize, ATTN_SMEM);
    cudaFuncSetAttribute(ffn_mma_kernel,  cudaFuncAttributeMaxDynamicSharedMemorySize, FFN_SMEM);
    cudaFuncSetAttribute(head2_kernel,    cudaFuncAttributeMaxDynamicSharedMemorySize, h2_smem);

    wprep_all_kernel<<<16, 256>>>(ffw1, ffb1, ffw2);
    for (int l = 0; l < 2; l++) {
        qkv_prep_kernel<<<128, 256>>>(x, (l == 0) ? 1 : 0, wqkv + l * 588, bqkv + l * 42);
        attn_mma_kernel<<<512, 256, ATTN_SMEM>>>();
        ffn_mma_kernel<<<256, 256, FFN_SMEM>>>(l, x, (l == 0) ? 1 : 0,
                                               wo + l * 196, bo + l * 14,
                                               ln1g + l * 14, ln1b + l * 14,
                                               ffb2 + l * 14, ln2g + l * 14, ln2b + l * 14,
                                               fc1w, fc1b, fc2w, fc2b, out);
    }
    head2_kernel<<<256, 256, h2_smem>>>(x, y, fc3w, fc3b, fc4w, fc4b, fc5w, fc5b, out);
}

// round 13
// speedup vs baseline: 1.0557x; 1.0557x over previous
#include <cuda_runtime.h>
#include <cuda_fp16.h>
#include <stdint.h>

#define NROWS 8192
#define DM 14
#define MF 36
#define EPS 1e-5f
#define NPART 6
typedef unsigned long long u64;

__device__ __align__(16) float g_h[NROWS * DM];
__device__ __align__(16) float g_q[NROWS * DM];   // pre-scaled by D^-0.5*log2(e)
__device__ __align__(16) float g_part[NPART * NROWS * 16];
__device__ __align__(16) __half g_kp[4 * NROWS * 8];   // [arr][key][8] f16
__device__ __align__(16) __half g_vt[32][NROWS];       // [dim-ish][key] f16
__device__ __align__(16) __half g_w1p[2 * 4 * 2048 * 8];  // per-layer W1 repack
__device__ __align__(16) __half g_w2p[2 * 32 * 2048];     // per-layer W2t repack
__device__ float g_sizef[NROWS];
__device__ float g_qn[NROWS];
__device__ float g_kmaxpart[128];

// ---- helpers ----
__device__ __forceinline__ u64 f2u(float2 v) { union { float2 f; u64 u; } c; c.f = v; return c.u; }
__device__ __forceinline__ float2 u2f(u64 u) { union { float2 f; u64 u; } c; c.u = u; return c.f; }
__device__ __forceinline__ u64 pack2(float lo, float hi) { float2 v; v.x = lo; v.y = hi; return f2u(v); }
__device__ __forceinline__ u64 fma2(u64 a, u64 b, u64 c) {
    u64 d; asm("fma.rn.f32x2 %0,%1,%2,%3;" : "=l"(d) : "l"(a), "l"(b), "l"(c)); return d;
}
__device__ __forceinline__ float ex2f(float x) {
    float y; asm("ex2.approx.f32 %0,%1;" : "=f"(y) : "f"(x)); return y;
}
__device__ __forceinline__ float wsum(float v) {
#pragma unroll
    for (int o = 16; o; o >>= 1) v += __shfl_xor_sync(0xffffffffu, v, o);
    return v;
}
__device__ __forceinline__ float wmax(float v) {
#pragma unroll
    for (int o = 16; o; o >>= 1) v = fmaxf(v, __shfl_xor_sync(0xffffffffu, v, o));
    return v;
}
__device__ __forceinline__ void cp16(uint32_t dst, const void* src) {
    asm volatile("cp.async.cg.shared.global [%0], [%1], 16;" :: "r"(dst), "l"(src));
}
#define CP_COMMIT() asm volatile("cp.async.commit_group;")
#define CP_WAIT(N)  asm volatile("cp.async.wait_group %0;" :: "n"(N))

__device__ __forceinline__ uint32_t h2pack(float a, float b) {
    __half2 h = __floats2half2_rn(a, b);
    return *(uint32_t*)&h;
}
__device__ __forceinline__ void mma16816(float* d, const uint32_t* a, const uint32_t* b, const float* c) {
    asm volatile(
        "mma.sync.aligned.m16n8k16.row.col.f32.f16.f16.f32 "
        "{%0,%1,%2,%3}, {%4,%5,%6,%7}, {%8,%9}, {%10,%11,%12,%13};"
        : "=f"(d[0]), "=f"(d[1]), "=f"(d[2]), "=f"(d[3])
        : "r"(a[0]), "r"(a[1]), "r"(a[2]), "r"(a[3]), "r"(b[0]), "r"(b[1]),
          "f"(c[0]), "f"(c[1]), "f"(c[2]), "f"(c[3]));
}

// ---------------- fused QKV projection + prep ----------------
#define QS 49
__global__ void __launch_bounds__(256, 1)
qkv_prep_kernel(const float* __restrict__ x0, int use_x,
                const float* __restrict__ W, const float* __restrict__ b) {
    __shared__ float Ws[42 * 14], bs[42], hs[64 * 14], qkvs[64 * QS], sp[2];
    const float* hin = use_x ? x0 : g_h;
    const int t = threadIdx.x;
    const int rb = blockIdx.x * 64;
    for (int i = t; i < 588; i += 256) Ws[i] = W[i];
    if (t < 42) bs[t] = b[t];
    for (int i = t; i < 64 * 14; i += 256) hs[i] = hin[rb * DM + i];
    __syncthreads();
    const float scale = rsqrtf(14.0f) * 1.44269504f;
    for (int idx = t; idx < 64 * 42; idx += 256) {
        int r = idx / 42, c = idx % 42;
        float s = bs[c];
#pragma unroll
        for (int d = 0; d < 14; d++) s = fmaf(hs[r * 14 + d], Ws[c * 14 + d], s);
        qkvs[r * QS + c] = (c < 14) ? s * scale : s;
    }
    __syncthreads();

    if (t < 64) {
        int row = rb + t;
        const float* qr = qkvs + t * QS;
        float qn = 0.f, kn = 0.f;
        float kv[14], vv[14];
#pragma unroll
        for (int d = 0; d < 14; d++) {
            float qf = qr[d];
            g_q[row * DM + d] = qf;
            qn = fmaf(qf, qf, qn);
            kv[d] = qr[14 + d]; kn = fmaf(kv[d], kv[d], kn);
            vv[d] = qr[28 + d];
        }
        g_qn[row] = sqrtf(qn);

        __half hi[16], lo[16];
#pragma unroll
        for (int d = 0; d < 14; d++) {
            hi[d] = __float2half_rn(kv[d]);
            lo[d] = __float2half_rn(kv[d] - __half2float(hi[d]));
        }
        hi[14] = __float2half_rn(1.0f); hi[15] = __float2half_rn(0.f);
        lo[14] = __float2half_rn(0.f);  lo[15] = __float2half_rn(0.f);
        {
            __half* p0 = g_kp + (0 * NROWS + row) * 8;
            __half* p1 = g_kp + (1 * NROWS + row) * 8;
            __half* p2 = g_kp + (2 * NROWS + row) * 8;
            __half* p3 = g_kp + (3 * NROWS + row) * 8;
#pragma unroll
            for (int d = 0; d < 8; d++) { p0[d] = hi[d]; p1[d] = hi[8 + d]; p2[d] = lo[d]; p3[d] = lo[8 + d]; }
        }
#pragma unroll
        for (int d = 0; d < 14; d++) {
            __half vh = __float2half_rn(vv[d]);
            g_vt[d][row] = vh;
            g_vt[16 + d][row] = __float2half_rn(vv[d] - __half2float(vh));
        }
        g_vt[14][row] = __float2half_rn(1.0f);
        g_vt[15][row] = __float2half_rn(0.f);
        g_vt[30][row] = __float2half_rn(0.f);
        g_vt[31][row] = __float2half_rn(0.f);

        kn = wmax(kn);
        if ((t & 31) == 0) sp[t >> 5] = kn;
    }
    __syncthreads();
    if (t == 0) g_kmaxpart[blockIdx.x] = fmaxf(sp[0], sp[1]);
}

// ---------------- mma.sync flash attention, 6-way key split (single wave) -------
// grid 384 = 64 q-tiles x 6 key-parts; 256 thr = 8 warps x 16 queries; 3 CTAs/SM.
#define KBUF 16384
#define BUFSTRIDE (16384 + 16896)
#define ATTN_SMEM (2 * BUFSTRIDE)
__constant__ int c_pstart[NPART + 1] = {0, 6, 12, 17, 22, 27, 32};  // chunk ranges

__device__ __forceinline__ void tile_cp2(uint32_t sbase, int buf, int key0c, int t) {
    uint32_t dst = sbase + (uint32_t)buf * BUFSTRIDE;
#pragma unroll
    for (int s = 0; s < 4; s++) {
        int i = t + s * 256;
        int a = i >> 8, key = i & 255;
        cp16(dst + (uint32_t)a * 4096 + (uint32_t)key * 16,
             g_kp + ((size_t)a * NROWS + key0c + key) * 8);
    }
#pragma unroll
    for (int s = 0; s < 4; s++) {
        int i = t + s * 256;
        int row = i >> 5, seg = i & 31;
        cp16(dst + KBUF + (uint32_t)row * 528 + (uint32_t)seg * 16,
             &g_vt[row][key0c + seg * 8]);
    }
}

__global__ void __launch_bounds__(256, 3)
attn_mma_kernel() {
    extern __shared__ char smc[];
    const int t = threadIdx.x, lane = t & 31, warp = t >> 5;
    const int g = lane >> 2, tg = lane & 3;
    const int tile = blockIdx.x / NPART, part = blockIdx.x - tile * NPART;
    const int cc0 = c_pstart[part], ccn = c_pstart[part + 1];
    const uint32_t sbase = (uint32_t)__cvta_generic_to_shared(smc);

    float mk2 = 0.f;
    for (int i = lane; i < 128; i += 32) mk2 = fmaxf(mk2, __ldg(g_kmaxpart + i));
    mk2 = wmax(mk2);
    const float maxk = sqrtf(mk2);

    const int qbase = tile * 128 + warp * 16;
    uint32_t qhi[4], qlo[4];
    {
        int r0 = qbase + g, r1 = r0 + 8;
        float v0a = g_q[r0 * DM + 2 * tg],     v1a = g_q[r0 * DM + 2 * tg + 1];
        float v0b = g_q[r1 * DM + 2 * tg],     v1b = g_q[r1 * DM + 2 * tg + 1];
        float v2a, v3a, v2b, v3b;
        if (tg < 3) {
            v2a = g_q[r0 * DM + 8 + 2 * tg]; v3a = g_q[r0 * DM + 9 + 2 * tg];
            v2b = g_q[r1 * DM + 8 + 2 * tg]; v3b = g_q[r1 * DM + 9 + 2 * tg];
        } else {
            v2a = -__ldg(g_qn + r0) * maxk; v3a = 0.f;
            v2b = -__ldg(g_qn + r1) * maxk; v3b = 0.f;
        }
        float vals[4][2] = {{v0a, v1a}, {v0b, v1b}, {v2a, v3a}, {v2b, v3b}};
#pragma unroll
        for (int i = 0; i < 4; i++) {
            qhi[i] = h2pack(vals[i][0], vals[i][1]);
            __half2 hh = *(__half2*)&qhi[i];
            qlo[i] = h2pack(vals[i][0] - __low2float(hh), vals[i][1] - __high2float(hh));
        }
    }

    float O0[4] = {0.f, 0.f, 0.f, 0.f};
    float O1[4] = {0.f, 0.f, 0.f, 0.f};

    tile_cp2(sbase, 0, cc0 * 256, t);
    CP_COMMIT();

    for (int c = cc0; c < ccn; c++) {
        const int cb = c - cc0;
        if (c < ccn - 1) {
            tile_cp2(sbase, (cb + 1) & 1, (c + 1) * 256, t);
            CP_COMMIT();
            CP_WAIT(1);
        } else {
            CP_WAIT(0);
        }
        __syncthreads();

        const char* kb = smc + (cb & 1) * BUFSTRIDE;
        const char* vb = kb + KBUF;

        for (int j = 0; j < 256; j += 16) {
            const char* k0 = kb + (size_t)(j + g) * 16 + tg * 4;
            const char* k1 = kb + (size_t)(j + 8 + g) * 16 + tg * 4;
            uint32_t bh0[2] = { *(const uint32_t*)k0,          *(const uint32_t*)(k0 + 4096) };
            uint32_t bl0[2] = { *(const uint32_t*)(k0 + 8192), *(const uint32_t*)(k0 + 12288) };
            uint32_t bh1[2] = { *(const uint32_t*)k1,          *(const uint32_t*)(k1 + 4096) };
            uint32_t bl1[2] = { *(const uint32_t*)(k1 + 8192), *(const uint32_t*)(k1 + 12288) };

            float S0[4] = {0.f, 0.f, 0.f, 0.f}, S1[4] = {0.f, 0.f, 0.f, 0.f};
            mma16816(S0, qhi, bh0, S0);
            mma16816(S0, qhi, bl0, S0);
            mma16816(S0, qlo, bh0, S0);
            mma16816(S1, qhi, bh1, S1);
            mma16816(S1, qhi, bl1, S1);
            mma16816(S1, qlo, bh1, S1);

            float p[8];
#pragma unroll
            for (int i = 0; i < 4; i++) { p[i] = ex2f(S0[i]); p[4 + i] = ex2f(S1[i]); }
            uint32_t phi[4], plo[4];
#pragma unroll
            for (int i = 0; i < 4; i++) {
                phi[i] = h2pack(p[2 * i], p[2 * i + 1]);
                __half2 hh = *(__half2*)&phi[i];
                plo[i] = h2pack(p[2 * i] - __low2float(hh), p[2 * i + 1] - __high2float(hh));
            }

            const char* v0 = vb + (size_t)(j * 2 + tg * 4);
            uint32_t vh0[2] = { *(const uint32_t*)(v0 + (size_t)g * 528),
                                *(const uint32_t*)(v0 + (size_t)g * 528 + 16) };
            uint32_t vh1[2] = { *(const uint32_t*)(v0 + (size_t)(8 + g) * 528),
                                *(const uint32_t*)(v0 + (size_t)(8 + g) * 528 + 16) };
            uint32_t vl0[2] = { *(const uint32_t*)(v0 + (size_t)(16 + g) * 528),
                                *(const uint32_t*)(v0 + (size_t)(16 + g) * 528 + 16) };
            uint32_t vl1[2] = { *(const uint32_t*)(v0 + (size_t)(24 + g) * 528),
                                *(const uint32_t*)(v0 + (size_t)(24 + g) * 528 + 16) };

            mma16816(O0, phi, vh0, O0);
            mma16816(O1, phi, vh1, O1);
            mma16816(O0, plo, vh0, O0);
            mma16816(O1, plo, vh1, O1);
            mma16816(O0, phi, vl0, O0);
            mma16816(O1, phi, vl1, O1);
        }
        __syncthreads();
    }

    {
        int r0 = qbase + g;
        float* d0 = g_part + ((size_t)part * NROWS + r0) * 16;
        float* d1 = g_part + ((size_t)part * NROWS + r0 + 8) * 16;
        *(float2*)(d0 + 2 * tg)     = make_float2(O0[0], O0[1]);
        *(float2*)(d0 + 8 + 2 * tg) = make_float2(O1[0], O1[1]);
        *(float2*)(d1 + 2 * tg)     = make_float2(O0[2], O0[3]);
        *(float2*)(d1 + 8 + 2 * tg) = make_float2(O1[2], O1[3]);
    }
}

// ---------------- combine: 8 threads/row, shuffle-distributed ----------------
__global__ void __launch_bounds__(256, 2)
combine_kernel(const float* __restrict__ x0, int use_x,
               const float* __restrict__ Wo, const float* __restrict__ bo,
               const float* __restrict__ lng, const float* __restrict__ lnb) {
    __shared__ float wos[196], bos[14];
    const int t = threadIdx.x, lane = t & 31;
    for (int i = t; i < 196; i += 256) wos[i] = Wo[i];
    if (t < 14) bos[t] = bo[t];
    __syncthreads();
    const float* hin = use_x ? x0 : g_h;
    const int row = blockIdx.x * 32 + (t >> 3);
    const int e = lane & 7;

    float2 acc = make_float2(0.f, 0.f);
#pragma unroll
    for (int p = 0; p < NPART; p++) {
        float2 v = ((const float2*)(g_part + ((size_t)p * NROWS + row) * 16))[e];
        acc.x += v.x; acc.y += v.y;
    }
    float l = __shfl_sync(0xffffffffu, acc.x, lane | 7);
    float inv = 1.f / l;
    float ax = acc.x * inv, ay = acc.y * inv;
    float a[14];
    const int base = lane & 24;
#pragma unroll
    for (int dp = 0; dp < 7; dp++) {
        a[2 * dp]     = __shfl_sync(0xffffffffu, ax, base + dp);
        a[2 * dp + 1] = __shfl_sync(0xffffffffu, ay, base + dp);
    }
    float pre0 = 0.f, pre1 = 0.f;
    if (e < 7) {
        int d2 = 2 * e;
        pre0 = bos[d2]; pre1 = bos[d2 + 1];
#pragma unroll
        for (int d = 0; d < 14; d++) {
            pre0 = fmaf(a[d], wos[d2 * 14 + d], pre0);
            pre1 = fmaf(a[d], wos[(d2 + 1) * 14 + d], pre1);
        }
        pre0 += hin[row * DM + d2];
        pre1 += hin[row * DM + d2 + 1];
    }
    float s = pre0 + pre1;
#pragma unroll
    for (int o = 4; o; o >>= 1) s += __shfl_xor_sync(0xffffffffu, s, o);
    float mu = s * (1.f / 14.f);
    float z0 = (e < 7) ? pre0 - mu : 0.f;
    float z1 = (e < 7) ? pre1 - mu : 0.f;
    float v = z0 * z0 + z1 * z1;
#pragma unroll
    for (int o = 4; o; o >>= 1) v += __shfl_xor_sync(0xffffffffu, v, o);
    float rs = rsqrtf(v * (1.f / 14.f) + EPS);
    if (e < 7) {
        int d2 = 2 * e;
        g_h[row * DM + d2]     = z0 * rs * __ldg(lng + d2)     + __ldg(lnb + d2);
        g_h[row * DM + d2 + 1] = z1 * rs * __ldg(lng + d2 + 1) + __ldg(lnb + d2 + 1);
    }
}

// ---------------- wprep (both layers, once) ----------------
__global__ void __launch_bounds__(256, 1)
wprep_all_kernel(const float* __restrict__ W1a, const float* __restrict__ b1a,
                 const float* __restrict__ W2a) {
    int idx = blockIdx.x * 256 + threadIdx.x;
    int layer = idx >> 11, j = idx & 2047;
    const float* W1 = W1a + layer * 28672;
    const float* b1 = b1a + layer * 2048;
    const float* W2 = W2a + layer * 28672;
    __half* w1p = g_w1p + layer * 65536;
    __half* w2p = g_w2p + layer * 65536;

    __half hi[16], lo[16];
#pragma unroll
    for (int d = 0; d < 14; d++) {
        float w = W1[j * 14 + d];
        hi[d] = __float2half_rn(w);
        lo[d] = __float2half_rn(w - __half2float(hi[d]));
    }
    {
        float bb = __ldg(b1 + j);
        hi[14] = __float2half_rn(bb);
        lo[14] = __float2half_rn(bb - __half2float(hi[14]));
        hi[15] = __float2half_rn(0.f); lo[15] = __float2half_rn(0.f);
    }
    {
        __half* p0 = w1p + (0 * 2048 + j) * 8;
        __half* p1 = w1p + (1 * 2048 + j) * 8;
        __half* p2 = w1p + (2 * 2048 + j) * 8;
        __half* p3 = w1p + (3 * 2048 + j) * 8;
#pragma unroll
        for (int d = 0; d < 8; d++) { p0[d] = hi[d]; p1[d] = hi[8 + d]; p2[d] = lo[d]; p3[d] = lo[8 + d]; }
    }
#pragma unroll
    for (int d = 0; d < 14; d++) {
        float w = W2[d * 2048 + j];
        __half wh = __float2half_rn(w);
        w2p[d * 2048 + j] = wh;
        w2p[(16 + d) * 2048 + j] = __float2half_rn(w - __half2float(wh));
    }
    w2p[14 * 2048 + j] = __float2half_rn(0.f);
    w2p[15 * 2048 + j] = __float2half_rn(0.f);
    w2p[30 * 2048 + j] = __float2half_rn(0.f);
    w2p[31 * 2048 + j] = __float2half_rn(0.f);
}

// ---------------- FFN via mma.sync (+fused head1 on layer 1) ----------------
#define FW1B 16384
#define FBUF (FW1B + 16896)
#define FFN_SMEM (2 * FBUF)
__device__ __forceinline__ void ffn_cp(uint32_t sbase, int buf, int chunk, int t, int layer) {
    uint32_t dst = sbase + (uint32_t)buf * FBUF;
    const __half* w1p = g_w1p + layer * 65536;
    const __half* w2p = g_w2p + layer * 65536;
#pragma unroll
    for (int s = 0; s < 4; s++) {
        int i = t + s * 256;
        int a = i >> 8, j = i & 255;
        cp16(dst + (uint32_t)a * 4096 + (uint32_t)j * 16,
             w1p + ((size_t)a * 2048 + chunk * 256 + j) * 8);
    }
#pragma unroll
    for (int s = 0; s < 4; s++) {
        int i = t + s * 256;
        int row = i >> 5, seg = i & 31;
        cp16(dst + FW1B + (uint32_t)row * 528 + (uint32_t)seg * 16,
             w2p + (size_t)row * 2048 + chunk * 256 + seg * 8);
    }
}

__global__ void __launch_bounds__(256, 2)
ffn_mma_kernel(int layer, const float* __restrict__ b2,
               const float* __restrict__ lng, const float* __restrict__ lnb,
               const float* __restrict__ fc1w, const float* __restrict__ fc1b,
               const float* __restrict__ fc2w, const float* __restrict__ fc2b,
               float* __restrict__ out) {
    extern __shared__ char smc[];
    const int t = threadIdx.x, lane = t & 31, warp = t >> 5;
    const int g = lane >> 2, tg = lane & 3;
    const int rw = warp & 1, jq = warp >> 1;
    const uint32_t sbase = (uint32_t)__cvta_generic_to_shared(smc);
    const int rbase = blockIdx.x * 32 + rw * 16;

    uint32_t qhi[4], qlo[4];
    {
        int r0 = rbase + g, r1 = r0 + 8;
        float v0a = g_h[r0 * DM + 2 * tg],     v1a = g_h[r0 * DM + 2 * tg + 1];
        float v0b = g_h[r1 * DM + 2 * tg],     v1b = g_h[r1 * DM + 2 * tg + 1];
        float v2a, v3a, v2b, v3b;
        if (tg < 3) {
            v2a = g_h[r0 * DM + 8 + 2 * tg]; v3a = g_h[r0 * DM + 9 + 2 * tg];
            v2b = g_h[r1 * DM + 8 + 2 * tg]; v3b = g_h[r1 * DM + 9 + 2 * tg];
        } else {
            v2a = 1.0f; v3a = 0.f;
            v2b = 1.0f; v3b = 0.f;
        }
        float vals[4][2] = {{v0a, v1a}, {v0b, v1b}, {v2a, v3a}, {v2b, v3b}};
#pragma unroll
        for (int i = 0; i < 4; i++) {
            qhi[i] = h2pack(vals[i][0], vals[i][1]);
            __half2 hh = *(__half2*)&qhi[i];
            qlo[i] = h2pack(vals[i][0] - __low2float(hh), vals[i][1] - __high2float(hh));
        }
    }

    float O0[4] = {0.f, 0.f, 0.f, 0.f};
    float O1[4] = {0.f, 0.f, 0.f, 0.f};

    ffn_cp(sbase, 0, 0, t, layer);
    CP_COMMIT();

    for (int c = 0; c < 8; c++) {
        if (c < 7) {
            ffn_cp(sbase, (c + 1) & 1, c + 1, t, layer);
            CP_COMMIT();
            CP_WAIT(1);
        } else {
            CP_WAIT(0);
        }
        __syncthreads();

        const char* kb = smc + (c & 1) * FBUF;
        const char* vb = kb + FW1B;

        for (int step = 0; step < 4; step++) {
            const int j = jq * 64 + step * 16;
            const char* k0 = kb + (size_t)(j + g) * 16 + tg * 4;
            const char* k1 = kb + (size_t)(j + 8 + g) * 16 + tg * 4;
            uint32_t bh0[2] = { *(const uint32_t*)k0,          *(const uint32_t*)(k0 + 4096) };
            uint32_t bl0[2] = { *(const uint32_t*)(k0 + 8192), *(const uint32_t*)(k0 + 12288) };
            uint32_t bh1[2] = { *(const uint32_t*)k1,          *(const uint32_t*)(k1 + 4096) };
            uint32_t bl1[2] = { *(const uint32_t*)(k1 + 8192), *(const uint32_t*)(k1 + 12288) };

            float S0[4] = {0.f, 0.f, 0.f, 0.f}, S1[4] = {0.f, 0.f, 0.f, 0.f};
            mma16816(S0, qhi, bh0, S0);
            mma16816(S0, qhi, bl0, S0);
            mma16816(S0, qlo, bh0, S0);
            mma16816(S1, qhi, bh1, S1);
            mma16816(S1, qhi, bl1, S1);
            mma16816(S1, qlo, bh1, S1);

            float p[8];
#pragma unroll
            for (int i = 0; i < 4; i++) { p[i] = fmaxf(S0[i], 0.f); p[4 + i] = fmaxf(S1[i], 0.f); }
            uint32_t phi[4], plo[4];
#pragma unroll
            for (int i = 0; i < 4; i++) {
                phi[i] = h2pack(p[2 * i], p[2 * i + 1]);
                __half2 hh = *(__half2*)&phi[i];
                plo[i] = h2pack(p[2 * i] - __low2float(hh), p[2 * i + 1] - __high2float(hh));
            }

            const char* v0 = vb + (size_t)(j * 2 + tg * 4);
            uint32_t vh0[2] = { *(const uint32_t*)(v0 + (size_t)g * 528),
                                *(const uint32_t*)(v0 + (size_t)g * 528 + 16) };
            uint32_t vh1[2] = { *(const uint32_t*)(v0 + (size_t)(8 + g) * 528),
                                *(const uint32_t*)(v0 + (size_t)(8 + g) * 528 + 16) };
            uint32_t vl0[2] = { *(const uint32_t*)(v0 + (size_t)(16 + g) * 528),
                                *(const uint32_t*)(v0 + (size_t)(16 + g) * 528 + 16) };
            uint32_t vl1[2] = { *(const uint32_t*)(v0 + (size_t)(24 + g) * 528),
                                *(const uint32_t*)(v0 + (size_t)(24 + g) * 528 + 16) };

            mma16816(O0, phi, vh0, O0);
            mma16816(O1, phi, vh1, O1);
            mma16816(O0, plo, vh0, O0);
            mma16816(O1, plo, vh1, O1);
            mma16816(O0, phi, vl0, O0);
            mma16816(O1, phi, vl1, O1);
        }
        __syncthreads();
    }

    {
        float* osum = (float*)smc;        // [grp][32][16] slices, buffers dead
        int lr = rw * 16 + g;
        float* om = osum + jq * 512;
        om[lr * 16 + 2 * tg]           = O0[0];
        om[lr * 16 + 2 * tg + 1]       = O0[1];
        om[lr * 16 + 8 + 2 * tg]       = O1[0];
        om[lr * 16 + 9 + 2 * tg]       = O1[1];
        om[(lr + 8) * 16 + 2 * tg]     = O0[2];
        om[(lr + 8) * 16 + 2 * tg + 1] = O0[3];
        om[(lr + 8) * 16 + 8 + 2 * tg] = O1[2];
        om[(lr + 8) * 16 + 9 + 2 * tg] = O1[3];
        __syncthreads();
        if (t < 32) {
            int row = blockIdx.x * 32 + t;
            float pre[14], mu = 0.f;
#pragma unroll
            for (int d = 0; d < 14; d++) {
                float v = osum[t * 16 + d] + osum[512 + t * 16 + d]
                        + osum[1024 + t * 16 + d] + osum[1536 + t * 16 + d]
                        + __ldg(b2 + d) + g_h[row * DM + d];
                pre[d] = v; mu += v;
            }
            mu *= (1.f / 14.f);
            float var = 0.f;
#pragma unroll
            for (int d = 0; d < 14; d++) { float z = pre[d] - mu; var = fmaf(z, z, var); }
            float rs = rsqrtf(var * (1.f / 14.f) + EPS);
            float hv[14];
#pragma unroll
            for (int d = 0; d < 14; d++) {
                hv[d] = (pre[d] - mu) * rs * __ldg(lng + d) + __ldg(lnb + d);
                g_h[row * DM + d] = hv[d];
            }
            if (layer == 1) {
                float size = __ldg(fc2b);
#pragma unroll
                for (int d2 = 0; d2 < 14; d2++) {
                    float s = __ldg(fc1b + d2);
#pragma unroll
                    for (int d = 0; d < 14; d++) s = fmaf(hv[d], __ldg(fc1w + d2 * 14 + d), s);
                    size = fmaf(s, __ldg(fc2w + d2), size);
                }
                out[row] = size;
                g_sizef[row] = (float)(int)size;
            }
        }
    }
}

// ---------------- head 2: 32 rows/CTA, w3 streamed from L2, occupancy 2 --------
__global__ void __launch_bounds__(256, 2)
head2_kernel(const float* __restrict__ x, const float* __restrict__ y,
             const float* __restrict__ w3, const float* __restrict__ b3,
             const float* __restrict__ w4, const float* __restrict__ b4,
             const float* __restrict__ w5, const float* __restrict__ b5,
             float* __restrict__ out) {
    extern __shared__ float sm[];
    float* ins = sm;             // 1632
    float* red = ins + 1632;     // 256
    float* r1f = red + 256;      // 8704
    float* w4s = r1f + 8704;     // 16640  -> total 27232 floats = 108.9KB
    const int t = threadIdx.x, lane = t & 31, warp = t >> 5;
    const int rbase = blockIdx.x * 32;
    for (int i = t; i < 32 * 51; i += 256) {
        int r = i / 51, c = i % 51, row = rbase + r;
        float v;
        if (c == 0)      v = g_sizef[row];
        else if (c < 15) v = x[row * DM + c - 1];
        else             v = y[row * MF + c - 15];
        ins[i] = v;
    }
    __syncthreads();

    // stage A: r1[neuron t][32 rows]; w3 row streamed from L2
    float r1a[32];
    float b3t = __ldg(b3 + t);
#pragma unroll
    for (int r = 0; r < 32; r++) r1a[r] = b3t;
    const float* w3r = w3 + t * 51;
    for (int i = 0; i < 51; i++) {
        float w = __ldg(w3r + i);
#pragma unroll
        for (int r = 0; r < 32; r++) r1a[r] = fmaf(ins[r * 51 + i], w, r1a[r]);
    }
#pragma unroll
    for (int rp = 0; rp < 16; rp++) {
        float2 v;
        v.x = fmaxf(r1a[2 * rp], 0.f);
        v.y = fmaxf(r1a[2 * rp + 1], 0.f);
        ((float2*)r1f)[t * 17 + rp] = v;
    }
    __syncthreads();

    u64 r2a2[16];
    float b4t = __ldg(b4 + t);
#pragma unroll
    for (int rp = 0; rp < 16; rp++) r2a2[rp] = pack2(b4t, b4t);
    for (int c = 0; c < 4; c++) {
        for (int i = t; i < 256 * 64; i += 256) {
            int o = i >> 6, jj = i & 63;
            w4s[o * 65 + jj] = __ldg(w4 + o * 256 + c * 64 + jj);
        }
        __syncthreads();
#pragma unroll 2
        for (int jj = 0; jj < 64; jj++) {
            float w = w4s[t * 65 + jj];
            u64 w2p = pack2(w, w);
            const float2* rp1 = ((const float2*)r1f) + (c * 64 + jj) * 17;
#pragma unroll
            for (int rp = 0; rp < 16; rp++) r2a2[rp] = fma2(f2u(rp1[rp]), w2p, r2a2[rp]);
        }
        __syncthreads();
    }

    float w5t = __ldg(w5 + t);
#pragma unroll
    for (int rp = 0; rp < 16; rp++) {
        float2 f = u2f(r2a2[rp]);
        float v0 = wsum(fmaxf(f.x, 0.f) * w5t);
        float v1 = wsum(fmaxf(f.y, 0.f) * w5t);
        if (lane == 0) {
            red[warp * 32 + 2 * rp] = v0;
            red[warp * 32 + 2 * rp + 1] = v1;
        }
    }
    __syncthreads();
    if (t < 32) {
        float s = __ldg(b5);
        for (int w = 0; w < 8; w++) s += red[w * 32 + t];
        int row = rbase + t;
        out[NROWS + row] = (g_sizef[row] != 0.f) ? s : 0.f;
    }
}

// ---------------- launcher ----------------
extern "C" void kernel_launch(void* const* d_in, const int* in_sizes, int n_in,
                              void* d_out, int out_size) {
    const float* x    = (const float*)d_in[0];
    const float* y    = (const float*)d_in[1];
    const float* wqkv = (const float*)d_in[2];
    const float* bqkv = (const float*)d_in[3];
    const float* wo   = (const float*)d_in[4];
    const float* bo   = (const float*)d_in[5];
    const float* ln1g = (const float*)d_in[6];
    const float* ln1b = (const float*)d_in[7];
    const float* ffw1 = (const float*)d_in[8];
    const float* ffb1 = (const float*)d_in[9];
    const float* ffw2 = (const float*)d_in[10];
    const float* ffb2 = (const float*)d_in[11];
    const float* ln2g = (const float*)d_in[12];
    const float* ln2b = (const float*)d_in[13];
    const float* fc1w = (const float*)d_in[14];
    const float* fc1b = (const float*)d_in[15];
    const float* fc2w = (const float*)d_in[16];
    const float* fc2b = (const float*)d_in[17];
    const float* fc3w = (const float*)d_in[18];
    const float* fc3b = (const float*)d_in[19];
    const float* fc4w = (const float*)d_in[20];
    const float* fc4b = (const float*)d_in[21];
    const float* fc5w = (const float*)d_in[22];
    const float* fc5b = (const float*)d_in[23];
    float* out = (float*)d_out;

    const int h2_smem = (1632 + 256 + 8704 + 16640) * (int)sizeof(float);
    cudaFuncSetAttribute(attn_mma_kernel, cudaFuncAttributeMaxDynamicSharedMemorySize, ATTN_SMEM);
    cudaFuncSetAttribute(ffn_mma_kernel,  cudaFuncAttributeMaxDynamicSharedMemorySize, FFN_SMEM);
    cudaFuncSetAttribute(head2_kernel,    cudaFuncAttributeMaxDynamicSharedMemorySize, h2_smem);

    wprep_all_kernel<<<16, 256>>>(ffw1, ffb1, ffw2);
    for (int l = 0; l < 2; l++) {
        qkv_prep_kernel<<<128, 256>>>(x, (l == 0) ? 1 : 0, wqkv + l * 588, bqkv + l * 42);
        attn_mma_kernel<<<64 * NPART, 256, ATTN_SMEM>>>();
        combine_kernel<<<256, 256>>>(x, (l == 0) ? 1 : 0, wo + l * 196, bo + l * 14,
                                     ln1g + l * 14, ln1b + l * 14);
        ffn_mma_kernel<<<256, 256, FFN_SMEM>>>(l, ffb2 + l * 14, ln2g + l * 14, ln2b + l * 14,
                                               fc1w, fc1b, fc2w, fc2b, out);
    }
    head2_kernel<<<256, 256, h2_smem>>>(x, y, fc3w, fc3b, fc4w, fc4b, fc5w, fc5b, out);
}

// round 14
// speedup vs baseline: 1.2865x; 1.2187x over previous
#include <cuda_runtime.h>
#include <cuda_fp16.h>
#include <stdint.h>

#define NROWS 8192
#define DM 14
#define MF 36
#define EPS 1e-5f
#define NPART 6
typedef unsigned long long u64;

__device__ __align__(16) float g_h[NROWS * DM];
__device__ __align__(16) float g_q[NROWS * DM];   // pre-scaled by D^-0.5*log2(e)
__device__ __align__(16) float g_part[NPART * NROWS * 16];
__device__ __align__(16) __half g_kp[4 * NROWS * 8];   // [arr][key][8] f16
__device__ __align__(16) __half g_vt[32][NROWS];       // [dim-ish][key] f16
__device__ __align__(16) __half g_w1p[2 * 4 * 2048 * 8];  // per-layer W1 repack
__device__ __align__(16) __half g_w2p[2 * 32 * 2048];     // per-layer W2t repack
__device__ __align__(16) __half g_w4p[16 * 4 * 256 * 8];  // fc4 repack [kstep][arr][o][8]
__device__ float g_sizef[NROWS];
__device__ float g_qn[NROWS];
__device__ float g_kmaxpart[128];

// ---- helpers ----
__device__ __forceinline__ u64 f2u(float2 v) { union { float2 f; u64 u; } c; c.f = v; return c.u; }
__device__ __forceinline__ float2 u2f(u64 u) { union { float2 f; u64 u; } c; c.u = u; return c.f; }
__device__ __forceinline__ u64 pack2(float lo, float hi) { float2 v; v.x = lo; v.y = hi; return f2u(v); }
__device__ __forceinline__ u64 fma2(u64 a, u64 b, u64 c) {
    u64 d; asm("fma.rn.f32x2 %0,%1,%2,%3;" : "=l"(d) : "l"(a), "l"(b), "l"(c)); return d;
}
__device__ __forceinline__ float ex2f(float x) {
    float y; asm("ex2.approx.f32 %0,%1;" : "=f"(y) : "f"(x)); return y;
}
__device__ __forceinline__ float wsum(float v) {
#pragma unroll
    for (int o = 16; o; o >>= 1) v += __shfl_xor_sync(0xffffffffu, v, o);
    return v;
}
__device__ __forceinline__ float wmax(float v) {
#pragma unroll
    for (int o = 16; o; o >>= 1) v = fmaxf(v, __shfl_xor_sync(0xffffffffu, v, o));
    return v;
}
__device__ __forceinline__ void cp16(uint32_t dst, const void* src) {
    asm volatile("cp.async.cg.shared.global [%0], [%1], 16;" :: "r"(dst), "l"(src));
}
#define CP_COMMIT() asm volatile("cp.async.commit_group;")
#define CP_WAIT(N)  asm volatile("cp.async.wait_group %0;" :: "n"(N))

__device__ __forceinline__ uint32_t h2pack(float a, float b) {
    __half2 h = __floats2half2_rn(a, b);
    return *(uint32_t*)&h;
}
__device__ __forceinline__ void mma16816(float* d, const uint32_t* a, const uint32_t* b, const float* c) {
    asm volatile(
        "mma.sync.aligned.m16n8k16.row.col.f32.f16.f16.f32 "
        "{%0,%1,%2,%3}, {%4,%5,%6,%7}, {%8,%9}, {%10,%11,%12,%13};"
        : "=f"(d[0]), "=f"(d[1]), "=f"(d[2]), "=f"(d[3])
        : "r"(a[0]), "r"(a[1]), "r"(a[2]), "r"(a[3]), "r"(b[0]), "r"(b[1]),
          "f"(c[0]), "f"(c[1]), "f"(c[2]), "f"(c[3]));
}

// ---------------- fused QKV projection + prep ----------------
#define QS 49
__global__ void __launch_bounds__(256, 1)
qkv_prep_kernel(const float* __restrict__ x0, int use_x,
                const float* __restrict__ W, const float* __restrict__ b) {
    __shared__ float Ws[42 * 14], bs[42], hs[64 * 14], qkvs[64 * QS], sp[2];
    const float* hin = use_x ? x0 : g_h;
    const int t = threadIdx.x;
    const int rb = blockIdx.x * 64;
    for (int i = t; i < 588; i += 256) Ws[i] = W[i];
    if (t < 42) bs[t] = b[t];
    for (int i = t; i < 64 * 14; i += 256) hs[i] = hin[rb * DM + i];
    __syncthreads();
    const float scale = rsqrtf(14.0f) * 1.44269504f;
    for (int idx = t; idx < 64 * 42; idx += 256) {
        int r = idx / 42, c = idx % 42;
        float s = bs[c];
#pragma unroll
        for (int d = 0; d < 14; d++) s = fmaf(hs[r * 14 + d], Ws[c * 14 + d], s);
        qkvs[r * QS + c] = (c < 14) ? s * scale : s;
    }
    __syncthreads();

    if (t < 64) {
        int row = rb + t;
        const float* qr = qkvs + t * QS;
        float qn = 0.f, kn = 0.f;
        float kv[14], vv[14];
#pragma unroll
        for (int d = 0; d < 14; d++) {
            float qf = qr[d];
            g_q[row * DM + d] = qf;
            qn = fmaf(qf, qf, qn);
            kv[d] = qr[14 + d]; kn = fmaf(kv[d], kv[d], kn);
            vv[d] = qr[28 + d];
        }
        g_qn[row] = sqrtf(qn);

        __half hi[16], lo[16];
#pragma unroll
        for (int d = 0; d < 14; d++) {
            hi[d] = __float2half_rn(kv[d]);
            lo[d] = __float2half_rn(kv[d] - __half2float(hi[d]));
        }
        hi[14] = __float2half_rn(1.0f); hi[15] = __float2half_rn(0.f);
        lo[14] = __float2half_rn(0.f);  lo[15] = __float2half_rn(0.f);
        {
            __half* p0 = g_kp + (0 * NROWS + row) * 8;
            __half* p1 = g_kp + (1 * NROWS + row) * 8;
            __half* p2 = g_kp + (2 * NROWS + row) * 8;
            __half* p3 = g_kp + (3 * NROWS + row) * 8;
#pragma unroll
            for (int d = 0; d < 8; d++) { p0[d] = hi[d]; p1[d] = hi[8 + d]; p2[d] = lo[d]; p3[d] = lo[8 + d]; }
        }
#pragma unroll
        for (int d = 0; d < 14; d++) {
            __half vh = __float2half_rn(vv[d]);
            g_vt[d][row] = vh;
            g_vt[16 + d][row] = __float2half_rn(vv[d] - __half2float(vh));
        }
        g_vt[14][row] = __float2half_rn(1.0f);
        g_vt[15][row] = __float2half_rn(0.f);
        g_vt[30][row] = __float2half_rn(0.f);
        g_vt[31][row] = __float2half_rn(0.f);

        kn = wmax(kn);
        if ((t & 31) == 0) sp[t >> 5] = kn;
    }
    __syncthreads();
    if (t == 0) g_kmaxpart[blockIdx.x] = fmaxf(sp[0], sp[1]);
}

// ---------------- mma.sync flash attention, 6-way key split (single wave) -------
#define KBUF 16384
#define BUFSTRIDE (16384 + 16896)
#define ATTN_SMEM (2 * BUFSTRIDE)
__constant__ int c_pstart[NPART + 1] = {0, 6, 12, 17, 22, 27, 32};

__device__ __forceinline__ void tile_cp2(uint32_t sbase, int buf, int key0c, int t) {
    uint32_t dst = sbase + (uint32_t)buf * BUFSTRIDE;
#pragma unroll
    for (int s = 0; s < 4; s++) {
        int i = t + s * 256;
        int a = i >> 8, key = i & 255;
        cp16(dst + (uint32_t)a * 4096 + (uint32_t)key * 16,
             g_kp + ((size_t)a * NROWS + key0c + key) * 8);
    }
#pragma unroll
    for (int s = 0; s < 4; s++) {
        int i = t + s * 256;
        int row = i >> 5, seg = i & 31;
        cp16(dst + KBUF + (uint32_t)row * 528 + (uint32_t)seg * 16,
             &g_vt[row][key0c + seg * 8]);
    }
}

__global__ void __launch_bounds__(256, 3)
attn_mma_kernel() {
    extern __shared__ char smc[];
    const int t = threadIdx.x, lane = t & 31, warp = t >> 5;
    const int g = lane >> 2, tg = lane & 3;
    const int tile = blockIdx.x / NPART, part = blockIdx.x - tile * NPART;
    const int cc0 = c_pstart[part], ccn = c_pstart[part + 1];
    const uint32_t sbase = (uint32_t)__cvta_generic_to_shared(smc);

    float mk2 = 0.f;
    for (int i = lane; i < 128; i += 32) mk2 = fmaxf(mk2, __ldg(g_kmaxpart + i));
    mk2 = wmax(mk2);
    const float maxk = sqrtf(mk2);

    const int qbase = tile * 128 + warp * 16;
    uint32_t qhi[4], qlo[4];
    {
        int r0 = qbase + g, r1 = r0 + 8;
        float v0a = g_q[r0 * DM + 2 * tg],     v1a = g_q[r0 * DM + 2 * tg + 1];
        float v0b = g_q[r1 * DM + 2 * tg],     v1b = g_q[r1 * DM + 2 * tg + 1];
        float v2a, v3a, v2b, v3b;
        if (tg < 3) {
            v2a = g_q[r0 * DM + 8 + 2 * tg]; v3a = g_q[r0 * DM + 9 + 2 * tg];
            v2b = g_q[r1 * DM + 8 + 2 * tg]; v3b = g_q[r1 * DM + 9 + 2 * tg];
        } else {
            v2a = -__ldg(g_qn + r0) * maxk; v3a = 0.f;
            v2b = -__ldg(g_qn + r1) * maxk; v3b = 0.f;
        }
        float vals[4][2] = {{v0a, v1a}, {v0b, v1b}, {v2a, v3a}, {v2b, v3b}};
#pragma unroll
        for (int i = 0; i < 4; i++) {
            qhi[i] = h2pack(vals[i][0], vals[i][1]);
            __half2 hh = *(__half2*)&qhi[i];
            qlo[i] = h2pack(vals[i][0] - __low2float(hh), vals[i][1] - __high2float(hh));
        }
    }

    float O0[4] = {0.f, 0.f, 0.f, 0.f};
    float O1[4] = {0.f, 0.f, 0.f, 0.f};

    tile_cp2(sbase, 0, cc0 * 256, t);
    CP_COMMIT();

    for (int c = cc0; c < ccn; c++) {
        const int cb = c - cc0;
        if (c < ccn - 1) {
            tile_cp2(sbase, (cb + 1) & 1, (c + 1) * 256, t);
            CP_COMMIT();
            CP_WAIT(1);
        } else {
            CP_WAIT(0);
        }
        __syncthreads();

        const char* kb = smc + (cb & 1) * BUFSTRIDE;
        const char* vb = kb + KBUF;

        for (int j = 0; j < 256; j += 16) {
            const char* k0 = kb + (size_t)(j + g) * 16 + tg * 4;
            const char* k1 = kb + (size_t)(j + 8 + g) * 16 + tg * 4;
            uint32_t bh0[2] = { *(const uint32_t*)k0,          *(const uint32_t*)(k0 + 4096) };
            uint32_t bl0[2] = { *(const uint32_t*)(k0 + 8192), *(const uint32_t*)(k0 + 12288) };
            uint32_t bh1[2] = { *(const uint32_t*)k1,          *(const uint32_t*)(k1 + 4096) };
            uint32_t bl1[2] = { *(const uint32_t*)(k1 + 8192), *(const uint32_t*)(k1 + 12288) };

            float S0[4] = {0.f, 0.f, 0.f, 0.f}, S1[4] = {0.f, 0.f, 0.f, 0.f};
            mma16816(S0, qhi, bh0, S0);
            mma16816(S0, qhi, bl0, S0);
            mma16816(S0, qlo, bh0, S0);
            mma16816(S1, qhi, bh1, S1);
            mma16816(S1, qhi, bl1, S1);
            mma16816(S1, qlo, bh1, S1);

            float p[8];
#pragma unroll
            for (int i = 0; i < 4; i++) { p[i] = ex2f(S0[i]); p[4 + i] = ex2f(S1[i]); }
            uint32_t phi[4], plo[4];
#pragma unroll
            for (int i = 0; i < 4; i++) {
                phi[i] = h2pack(p[2 * i], p[2 * i + 1]);
                __half2 hh = *(__half2*)&phi[i];
                plo[i] = h2pack(p[2 * i] - __low2float(hh), p[2 * i + 1] - __high2float(hh));
            }

            const char* v0 = vb + (size_t)(j * 2 + tg * 4);
            uint32_t vh0[2] = { *(const uint32_t*)(v0 + (size_t)g * 528),
                                *(const uint32_t*)(v0 + (size_t)g * 528 + 16) };
            uint32_t vh1[2] = { *(const uint32_t*)(v0 + (size_t)(8 + g) * 528),
                                *(const uint32_t*)(v0 + (size_t)(8 + g) * 528 + 16) };
            uint32_t vl0[2] = { *(const uint32_t*)(v0 + (size_t)(16 + g) * 528),
                                *(const uint32_t*)(v0 + (size_t)(16 + g) * 528 + 16) };
            uint32_t vl1[2] = { *(const uint32_t*)(v0 + (size_t)(24 + g) * 528),
                                *(const uint32_t*)(v0 + (size_t)(24 + g) * 528 + 16) };

            mma16816(O0, phi, vh0, O0);
            mma16816(O1, phi, vh1, O1);
            mma16816(O0, plo, vh0, O0);
            mma16816(O1, plo, vh1, O1);
            mma16816(O0, phi, vl0, O0);
            mma16816(O1, phi, vl1, O1);
        }
        __syncthreads();
    }

    {
        int r0 = qbase + g;
        float* d0 = g_part + ((size_t)part * NROWS + r0) * 16;
        float* d1 = g_part + ((size_t)part * NROWS + r0 + 8) * 16;
        *(float2*)(d0 + 2 * tg)     = make_float2(O0[0], O0[1]);
        *(float2*)(d0 + 8 + 2 * tg) = make_float2(O1[0], O1[1]);
        *(float2*)(d1 + 2 * tg)     = make_float2(O0[2], O0[3]);
        *(float2*)(d1 + 8 + 2 * tg) = make_float2(O1[2], O1[3]);
    }
}

// ---------------- combine: 8 threads/row, shuffle-distributed ----------------
__global__ void __launch_bounds__(256, 2)
combine_kernel(const float* __restrict__ x0, int use_x,
               const float* __restrict__ Wo, const float* __restrict__ bo,
               const float* __restrict__ lng, const float* __restrict__ lnb) {
    __shared__ float wos[196], bos[14];
    const int t = threadIdx.x, lane = t & 31;
    for (int i = t; i < 196; i += 256) wos[i] = Wo[i];
    if (t < 14) bos[t] = bo[t];
    __syncthreads();
    const float* hin = use_x ? x0 : g_h;
    const int row = blockIdx.x * 32 + (t >> 3);
    const int e = lane & 7;

    float2 acc = make_float2(0.f, 0.f);
#pragma unroll
    for (int p = 0; p < NPART; p++) {
        float2 v = ((const float2*)(g_part + ((size_t)p * NROWS + row) * 16))[e];
        acc.x += v.x; acc.y += v.y;
    }
    float l = __shfl_sync(0xffffffffu, acc.x, lane | 7);
    float inv = 1.f / l;
    float ax = acc.x * inv, ay = acc.y * inv;
    float a[14];
    const int base = lane & 24;
#pragma unroll
    for (int dp = 0; dp < 7; dp++) {
        a[2 * dp]     = __shfl_sync(0xffffffffu, ax, base + dp);
        a[2 * dp + 1] = __shfl_sync(0xffffffffu, ay, base + dp);
    }
    float pre0 = 0.f, pre1 = 0.f;
    if (e < 7) {
        int d2 = 2 * e;
        pre0 = bos[d2]; pre1 = bos[d2 + 1];
#pragma unroll
        for (int d = 0; d < 14; d++) {
            pre0 = fmaf(a[d], wos[d2 * 14 + d], pre0);
            pre1 = fmaf(a[d], wos[(d2 + 1) * 14 + d], pre1);
        }
        pre0 += hin[row * DM + d2];
        pre1 += hin[row * DM + d2 + 1];
    }
    float s = pre0 + pre1;
#pragma unroll
    for (int o = 4; o; o >>= 1) s += __shfl_xor_sync(0xffffffffu, s, o);
    float mu = s * (1.f / 14.f);
    float z0 = (e < 7) ? pre0 - mu : 0.f;
    float z1 = (e < 7) ? pre1 - mu : 0.f;
    float v = z0 * z0 + z1 * z1;
#pragma unroll
    for (int o = 4; o; o >>= 1) v += __shfl_xor_sync(0xffffffffu, v, o);
    float rs = rsqrtf(v * (1.f / 14.f) + EPS);
    if (e < 7) {
        int d2 = 2 * e;
        g_h[row * DM + d2]     = z0 * rs * __ldg(lng + d2)     + __ldg(lnb + d2);
        g_h[row * DM + d2 + 1] = z1 * rs * __ldg(lng + d2 + 1) + __ldg(lnb + d2 + 1);
    }
}

// ---------------- wprep (FFN weights, both layers, once) ----------------
__global__ void __launch_bounds__(256, 1)
wprep_all_kernel(const float* __restrict__ W1a, const float* __restrict__ b1a,
                 const float* __restrict__ W2a) {
    int idx = blockIdx.x * 256 + threadIdx.x;
    int layer = idx >> 11, j = idx & 2047;
    const float* W1 = W1a + layer * 28672;
    const float* b1 = b1a + layer * 2048;
    const float* W2 = W2a + layer * 28672;
    __half* w1p = g_w1p + layer * 65536;
    __half* w2p = g_w2p + layer * 65536;

    __half hi[16], lo[16];
#pragma unroll
    for (int d = 0; d < 14; d++) {
        float w = W1[j * 14 + d];
        hi[d] = __float2half_rn(w);
        lo[d] = __float2half_rn(w - __half2float(hi[d]));
    }
    {
        float bb = __ldg(b1 + j);
        hi[14] = __float2half_rn(bb);
        lo[14] = __float2half_rn(bb - __half2float(hi[14]));
        hi[15] = __float2half_rn(0.f); lo[15] = __float2half_rn(0.f);
    }
    {
        __half* p0 = w1p + (0 * 2048 + j) * 8;
        __half* p1 = w1p + (1 * 2048 + j) * 8;
        __half* p2 = w1p + (2 * 2048 + j) * 8;
        __half* p3 = w1p + (3 * 2048 + j) * 8;
#pragma unroll
        for (int d = 0; d < 8; d++) { p0[d] = hi[d]; p1[d] = hi[8 + d]; p2[d] = lo[d]; p3[d] = lo[8 + d]; }
    }
#pragma unroll
    for (int d = 0; d < 14; d++) {
        float w = W2[d * 2048 + j];
        __half wh = __float2half_rn(w);
        w2p[d * 2048 + j] = wh;
        w2p[(16 + d) * 2048 + j] = __float2half_rn(w - __half2float(wh));
    }
    w2p[14 * 2048 + j] = __float2half_rn(0.f);
    w2p[15 * 2048 + j] = __float2half_rn(0.f);
    w2p[30 * 2048 + j] = __float2half_rn(0.f);
    w2p[31 * 2048 + j] = __float2half_rn(0.f);
}

// ---------------- wprep4 (fc4 repack, once) ----------------
// g_w4p[((kstep*4 + arr)*256 + o)*8 + e]; arr0/1 = hi (j lo/hi 8), arr2/3 = lo
__global__ void __launch_bounds__(256, 1)
wprep4_kernel(const float* __restrict__ w4) {
    int idx = blockIdx.x * 256 + threadIdx.x;    // 4096 = 16 ksteps x 256 o
    int kstep = idx >> 8, o = idx & 255;
#pragma unroll
    for (int e = 0; e < 8; e++) {
        float wa = w4[o * 256 + kstep * 16 + e];
        float wb = w4[o * 256 + kstep * 16 + 8 + e];
        __half ha = __float2half_rn(wa);
        __half hb = __float2half_rn(wb);
        g_w4p[((kstep * 4 + 0) * 256 + o) * 8 + e] = ha;
        g_w4p[((kstep * 4 + 1) * 256 + o) * 8 + e] = hb;
        g_w4p[((kstep * 4 + 2) * 256 + o) * 8 + e] = __float2half_rn(wa - __half2float(ha));
        g_w4p[((kstep * 4 + 3) * 256 + o) * 8 + e] = __float2half_rn(wb - __half2float(hb));
    }
}

// ---------------- FFN via mma.sync (+fused head1 on layer 1) ----------------
#define FW1B 16384
#define FBUF (FW1B + 16896)
#define FFN_SMEM (2 * FBUF)
__device__ __forceinline__ void ffn_cp(uint32_t sbase, int buf, int chunk, int t, int layer) {
    uint32_t dst = sbase + (uint32_t)buf * FBUF;
    const __half* w1p = g_w1p + layer * 65536;
    const __half* w2p = g_w2p + layer * 65536;
#pragma unroll
    for (int s = 0; s < 4; s++) {
        int i = t + s * 256;
        int a = i >> 8, j = i & 255;
        cp16(dst + (uint32_t)a * 4096 + (uint32_t)j * 16,
             w1p + ((size_t)a * 2048 + chunk * 256 + j) * 8);
    }
#pragma unroll
    for (int s = 0; s < 4; s++) {
        int i = t + s * 256;
        int row = i >> 5, seg = i & 31;
        cp16(dst + FW1B + (uint32_t)row * 528 + (uint32_t)seg * 16,
             w2p + (size_t)row * 2048 + chunk * 256 + seg * 8);
    }
}

__global__ void __launch_bounds__(256, 2)
ffn_mma_kernel(int layer, const float* __restrict__ b2,
               const float* __restrict__ lng, const float* __restrict__ lnb,
               const float* __restrict__ fc1w, const float* __restrict__ fc1b,
               const float* __restrict__ fc2w, const float* __restrict__ fc2b,
               float* __restrict__ out) {
    extern __shared__ char smc[];
    const int t = threadIdx.x, lane = t & 31, warp = t >> 5;
    const int g = lane >> 2, tg = lane & 3;
    const int rw = warp & 1, jq = warp >> 1;
    const uint32_t sbase = (uint32_t)__cvta_generic_to_shared(smc);
    const int rbase = blockIdx.x * 32 + rw * 16;

    uint32_t qhi[4], qlo[4];
    {
        int r0 = rbase + g, r1 = r0 + 8;
        float v0a = g_h[r0 * DM + 2 * tg],     v1a = g_h[r0 * DM + 2 * tg + 1];
        float v0b = g_h[r1 * DM + 2 * tg],     v1b = g_h[r1 * DM + 2 * tg + 1];
        float v2a, v3a, v2b, v3b;
        if (tg < 3) {
            v2a = g_h[r0 * DM + 8 + 2 * tg]; v3a = g_h[r0 * DM + 9 + 2 * tg];
            v2b = g_h[r1 * DM + 8 + 2 * tg]; v3b = g_h[r1 * DM + 9 + 2 * tg];
        } else {
            v2a = 1.0f; v3a = 0.f;
            v2b = 1.0f; v3b = 0.f;
        }
        float vals[4][2] = {{v0a, v1a}, {v0b, v1b}, {v2a, v3a}, {v2b, v3b}};
#pragma unroll
        for (int i = 0; i < 4; i++) {
            qhi[i] = h2pack(vals[i][0], vals[i][1]);
            __half2 hh = *(__half2*)&qhi[i];
            qlo[i] = h2pack(vals[i][0] - __low2float(hh), vals[i][1] - __high2float(hh));
        }
    }

    float O0[4] = {0.f, 0.f, 0.f, 0.f};
    float O1[4] = {0.f, 0.f, 0.f, 0.f};

    ffn_cp(sbase, 0, 0, t, layer);
    CP_COMMIT();

    for (int c = 0; c < 8; c++) {
        if (c < 7) {
            ffn_cp(sbase, (c + 1) & 1, c + 1, t, layer);
            CP_COMMIT();
            CP_WAIT(1);
        } else {
            CP_WAIT(0);
        }
        __syncthreads();

        const char* kb = smc + (c & 1) * FBUF;
        const char* vb = kb + FW1B;

        for (int step = 0; step < 4; step++) {
            const int j = jq * 64 + step * 16;
            const char* k0 = kb + (size_t)(j + g) * 16 + tg * 4;
            const char* k1 = kb + (size_t)(j + 8 + g) * 16 + tg * 4;
            uint32_t bh0[2] = { *(const uint32_t*)k0,          *(const uint32_t*)(k0 + 4096) };
            uint32_t bl0[2] = { *(const uint32_t*)(k0 + 8192), *(const uint32_t*)(k0 + 12288) };
            uint32_t bh1[2] = { *(const uint32_t*)k1,          *(const uint32_t*)(k1 + 4096) };
            uint32_t bl1[2] = { *(const uint32_t*)(k1 + 8192), *(const uint32_t*)(k1 + 12288) };

            float S0[4] = {0.f, 0.f, 0.f, 0.f}, S1[4] = {0.f, 0.f, 0.f, 0.f};
            mma16816(S0, qhi, bh0, S0);
            mma16816(S0, qhi, bl0, S0);
            mma16816(S0, qlo, bh0, S0);
            mma16816(S1, qhi, bh1, S1);
            mma16816(S1, qhi, bl1, S1);
            mma16816(S1, qlo, bh1, S1);

            float p[8];
#pragma unroll
            for (int i = 0; i < 4; i++) { p[i] = fmaxf(S0[i], 0.f); p[4 + i] = fmaxf(S1[i], 0.f); }
            uint32_t phi[4], plo[4];
#pragma unroll
            for (int i = 0; i < 4; i++) {
                phi[i] = h2pack(p[2 * i], p[2 * i + 1]);
                __half2 hh = *(__half2*)&phi[i];
                plo[i] = h2pack(p[2 * i] - __low2float(hh), p[2 * i + 1] - __high2float(hh));
            }

            const char* v0 = vb + (size_t)(j * 2 + tg * 4);
            uint32_t vh0[2] = { *(const uint32_t*)(v0 + (size_t)g * 528),
                                *(const uint32_t*)(v0 + (size_t)g * 528 + 16) };
            uint32_t vh1[2] = { *(const uint32_t*)(v0 + (size_t)(8 + g) * 528),
                                *(const uint32_t*)(v0 + (size_t)(8 + g) * 528 + 16) };
            uint32_t vl0[2] = { *(const uint32_t*)(v0 + (size_t)(16 + g) * 528),
                                *(const uint32_t*)(v0 + (size_t)(16 + g) * 528 + 16) };
            uint32_t vl1[2] = { *(const uint32_t*)(v0 + (size_t)(24 + g) * 528),
                                *(const uint32_t*)(v0 + (size_t)(24 + g) * 528 + 16) };

            mma16816(O0, phi, vh0, O0);
            mma16816(O1, phi, vh1, O1);
            mma16816(O0, plo, vh0, O0);
            mma16816(O1, plo, vh1, O1);
            mma16816(O0, phi, vl0, O0);
            mma16816(O1, phi, vl1, O1);
        }
        __syncthreads();
    }

    {
        float* osum = (float*)smc;
        int lr = rw * 16 + g;
        float* om = osum + jq * 512;
        om[lr * 16 + 2 * tg]           = O0[0];
        om[lr * 16 + 2 * tg + 1]       = O0[1];
        om[lr * 16 + 8 + 2 * tg]       = O1[0];
        om[lr * 16 + 9 + 2 * tg]       = O1[1];
        om[(lr + 8) * 16 + 2 * tg]     = O0[2];
        om[(lr + 8) * 16 + 2 * tg + 1] = O0[3];
        om[(lr + 8) * 16 + 8 + 2 * tg] = O1[2];
        om[(lr + 8) * 16 + 9 + 2 * tg] = O1[3];
        __syncthreads();
        if (t < 32) {
            int row = blockIdx.x * 32 + t;
            float pre[14], mu = 0.f;
#pragma unroll
            for (int d = 0; d < 14; d++) {
                float v = osum[t * 16 + d] + osum[512 + t * 16 + d]
                        + osum[1024 + t * 16 + d] + osum[1536 + t * 16 + d]
                        + __ldg(b2 + d) + g_h[row * DM + d];
                pre[d] = v; mu += v;
            }
            mu *= (1.f / 14.f);
            float var = 0.f;
#pragma unroll
            for (int d = 0; d < 14; d++) { float z = pre[d] - mu; var = fmaf(z, z, var); }
            float rs = rsqrtf(var * (1.f / 14.f) + EPS);
            float hv[14];
#pragma unroll
            for (int d = 0; d < 14; d++) {
                hv[d] = (pre[d] - mu) * rs * __ldg(lng + d) + __ldg(lnb + d);
                g_h[row * DM + d] = hv[d];
            }
            if (layer == 1) {
                float size = __ldg(fc2b);
#pragma unroll
                for (int d2 = 0; d2 < 14; d2++) {
                    float s = __ldg(fc1b + d2);
#pragma unroll
                    for (int d = 0; d < 14; d++) s = fmaf(hv[d], __ldg(fc1w + d2 * 14 + d), s);
                    size = fmaf(s, __ldg(fc2w + d2), size);
                }
                out[row] = size;
                g_sizef[row] = (float)(int)size;
            }
        }
    }
}

// ---------------- head2 via mma.sync: fc3 scalar + fc4 MMA + fc5 reduce --------
// grid 256 x 256 thr; 32 rows/CTA; warps = 2 row-halves x 4 o-quarters.
// smem: [0,32KB) W4 double buffer; then ins(6528B), r1h/r1l(16896B each), red(512B)
#define H2WB 16384
#define H2_INS   (2 * H2WB)
#define H2_R1H   (H2_INS + 1632 * 4)
#define H2_R1L   (H2_R1H + 32 * 264 * 2)
#define H2_RED   (H2_R1L + 32 * 264 * 2)
#define H2_SMEM  (H2_RED + 128 * 4)
__device__ __forceinline__ void h2cp(uint32_t sbase, int buf, int kstep, int t) {
    uint32_t dst = sbase + (uint32_t)buf * H2WB;
    const __half* src = g_w4p + (size_t)kstep * 8192;
#pragma unroll
    for (int s = 0; s < 4; s++) {
        int i = t + s * 256;                 // 1024 segs of 16B
        cp16(dst + (uint32_t)i * 16, src + (size_t)i * 8);
    }
}

__global__ void __launch_bounds__(256, 2)
head2_mma_kernel(const float* __restrict__ x, const float* __restrict__ y,
                 const float* __restrict__ w3, const float* __restrict__ b3,
                 const float* __restrict__ b4,
                 const float* __restrict__ w5, const float* __restrict__ b5,
                 float* __restrict__ out) {
    extern __shared__ char smc[];
    float*  ins = (float*)(smc + H2_INS);
    __half* r1h = (__half*)(smc + H2_R1H);
    __half* r1l = (__half*)(smc + H2_R1L);
    float*  red = (float*)(smc + H2_RED);
    const int t = threadIdx.x, lane = t & 31, warp = t >> 5;
    const int g = lane >> 2, tg = lane & 3;
    const int rw = warp & 1, nq = warp >> 1;
    const uint32_t sbase = (uint32_t)__cvta_generic_to_shared(smc);
    const int rbase = blockIdx.x * 32;

    // prefetch W4 ksteps 0,1 before the scalar stage
    h2cp(sbase, 0, 0, t);
    CP_COMMIT();
    h2cp(sbase, 1, 1, t);
    CP_COMMIT();

    for (int i = t; i < 32 * 51; i += 256) {
        int r = i / 51, c = i % 51, row = rbase + r;
        float v;
        if (c == 0)      v = g_sizef[row];
        else if (c < 15) v = x[row * DM + c - 1];
        else             v = y[row * MF + c - 15];
        ins[i] = v;
    }
    __syncthreads();

    // stage A: r1[neuron t][32 rows], relu, store f16 hi/lo
    {
        float r1a[32];
        float b3t = __ldg(b3 + t);
#pragma unroll
        for (int r = 0; r < 32; r++) r1a[r] = b3t;
        const float* w3r = w3 + t * 51;
        for (int i = 0; i < 51; i++) {
            float w = __ldg(w3r + i);
#pragma unroll
            for (int r = 0; r < 32; r++) r1a[r] = fmaf(ins[r * 51 + i], w, r1a[r]);
        }
#pragma unroll
        for (int r = 0; r < 32; r++) {
            float v = fmaxf(r1a[r], 0.f);
            __half h = __float2half_rn(v);
            r1h[r * 264 + t] = h;
            r1l[r * 264 + t] = __float2half_rn(v - __half2float(h));
        }
    }
    __syncthreads();

    // stage B: r2 = r1 @ W4^T via MMA; O[nt][4] covers o = nq*64 + nt*8 + {2tg,2tg+1}
    float O[8][4];
#pragma unroll
    for (int nt = 0; nt < 8; nt++)
#pragma unroll
        for (int i = 0; i < 4; i++) O[nt][i] = 0.f;

    const int r0 = rw * 16 + g;
    for (int kstep = 0; kstep < 16; kstep++) {
        CP_WAIT(1);
        __syncthreads();

        const int kb2 = kstep * 16 + 2 * tg;
        uint32_t ahi[4], alo[4];
        ahi[0] = *(const uint32_t*)&r1h[r0 * 264 + kb2];
        ahi[1] = *(const uint32_t*)&r1h[(r0 + 8) * 264 + kb2];
        ahi[2] = *(const uint32_t*)&r1h[r0 * 264 + kb2 + 8];
        ahi[3] = *(const uint32_t*)&r1h[(r0 + 8) * 264 + kb2 + 8];
        alo[0] = *(const uint32_t*)&r1l[r0 * 264 + kb2];
        alo[1] = *(const uint32_t*)&r1l[(r0 + 8) * 264 + kb2];
        alo[2] = *(const uint32_t*)&r1l[r0 * 264 + kb2 + 8];
        alo[3] = *(const uint32_t*)&r1l[(r0 + 8) * 264 + kb2 + 8];

        const char* wb = smc + (kstep & 1) * H2WB;
#pragma unroll
        for (int nt = 0; nt < 8; nt++) {
            int o0 = nq * 64 + nt * 8;
            const char* p = wb + (size_t)(o0 + g) * 16 + tg * 4;
            uint32_t bh[2] = { *(const uint32_t*)p,          *(const uint32_t*)(p + 4096) };
            uint32_t bl[2] = { *(const uint32_t*)(p + 8192), *(const uint32_t*)(p + 12288) };
            mma16816(O[nt], ahi, bh, O[nt]);
            mma16816(O[nt], ahi, bl, O[nt]);
            mma16816(O[nt], alo, bh, O[nt]);
        }
        __syncthreads();
        if (kstep + 2 < 16) {
            h2cp(sbase, kstep & 1, kstep + 2, t);
            CP_COMMIT();
        }
    }

    // stage C: +b4, relu, x w5, reduce
    float s0 = 0.f, s1 = 0.f;
#pragma unroll
    for (int nt = 0; nt < 8; nt++) {
        int o = nq * 64 + nt * 8 + 2 * tg;
        float b4a = __ldg(b4 + o),     b4b = __ldg(b4 + o + 1);
        float w5a = __ldg(w5 + o),     w5b = __ldg(w5 + o + 1);
        s0 += fmaxf(O[nt][0] + b4a, 0.f) * w5a + fmaxf(O[nt][1] + b4b, 0.f) * w5b;
        s1 += fmaxf(O[nt][2] + b4a, 0.f) * w5a + fmaxf(O[nt][3] + b4b, 0.f) * w5b;
    }
    s0 += __shfl_xor_sync(0xffffffffu, s0, 1); s0 += __shfl_xor_sync(0xffffffffu, s0, 2);
    s1 += __shfl_xor_sync(0xffffffffu, s1, 1); s1 += __shfl_xor_sync(0xffffffffu, s1, 2);
    if (tg == 0) {
        red[nq * 32 + r0] = s0;
        red[nq * 32 + r0 + 8] = s1;
    }
    __syncthreads();
    if (t < 32) {
        int row = rbase + t;
        float s = __ldg(b5) + red[t] + red[32 + t] + red[64 + t] + red[96 + t];
        out[NROWS + row] = (g_sizef[row] != 0.f) ? s : 0.f;
    }
}

// ---------------- launcher ----------------
extern "C" void kernel_launch(void* const* d_in, const int* in_sizes, int n_in,
                              void* d_out, int out_size) {
    const float* x    = (const float*)d_in[0];
    const float* y    = (const float*)d_in[1];
    const float* wqkv = (const float*)d_in[2];
    const float* bqkv = (const float*)d_in[3];
    const float* wo   = (const float*)d_in[4];
    const float* bo   = (const float*)d_in[5];
    const float* ln1g = (const float*)d_in[6];
    const float* ln1b = (const float*)d_in[7];
    const float* ffw1 = (const float*)d_in[8];
    const float* ffb1 = (const float*)d_in[9];
    const float* ffw2 = (const float*)d_in[10];
    const float* ffb2 = (const float*)d_in[11];
    const float* ln2g = (const float*)d_in[12];
    const float* ln2b = (const float*)d_in[13];
    const float* fc1w = (const float*)d_in[14];
    const float* fc1b = (const float*)d_in[15];
    const float* fc2w = (const float*)d_in[16];
    const float* fc2b = (const float*)d_in[17];
    const float* fc3w = (const float*)d_in[18];
    const float* fc3b = (const float*)d_in[19];
    const float* fc4w = (const float*)d_in[20];
    const float* fc4b = (const float*)d_in[21];
    const float* fc5w = (const float*)d_in[22];
    const float* fc5b = (const float*)d_in[23];
    float* out = (float*)d_out;

    cudaFuncSetAttribute(attn_mma_kernel,  cudaFuncAttributeMaxDynamicSharedMemorySize, ATTN_SMEM);
    cudaFuncSetAttribute(ffn_mma_kernel,   cudaFuncAttributeMaxDynamicSharedMemorySize, FFN_SMEM);
    cudaFuncSetAttribute(head2_mma_kernel, cudaFuncAttributeMaxDynamicSharedMemorySize, H2_SMEM);

    wprep_all_kernel<<<16, 256>>>(ffw1, ffb1, ffw2);
    wprep4_kernel<<<16, 256>>>(fc4w);
    for (int l = 0; l < 2; l++) {
        qkv_prep_kernel<<<128, 256>>>(x, (l == 0) ? 1 : 0, wqkv + l * 588, bqkv + l * 42);
        attn_mma_kernel<<<64 * NPART, 256, ATTN_SMEM>>>();
        combine_kernel<<<256, 256>>>(x, (l == 0) ? 1 : 0, wo + l * 196, bo + l * 14,
                                     ln1g + l * 14, ln1b + l * 14);
        ffn_mma_kernel<<<256, 256, FFN_SMEM>>>(l, ffb2 + l * 14, ln2g + l * 14, ln2b + l * 14,
                                               fc1w, fc1b, fc2w, fc2b, out);
    }
    head2_mma_kernel<<<256, 256, H2_SMEM>>>(x, y, fc3w, fc3b, fc4b, fc5w, fc5b, out);
}

// round 15
// speedup vs baseline: 1.4749x; 1.1464x over previous
#include <cuda_runtime.h>
#include <cuda_fp16.h>
#include <stdint.h>

#define NROWS 8192
#define DM 14
#define MF 36
#define EPS 1e-5f
#define NPART 6
typedef unsigned long long u64;

__device__ __align__(16) float g_h[NROWS * DM];
__device__ __align__(16) float g_q[NROWS * DM];   // pre-scaled by D^-0.5*log2(e)
__device__ __align__(16) float g_part[NPART * NROWS * 16];
__device__ __align__(16) __half g_kp[4 * NROWS * 8];   // [arr][key][8] f16
__device__ __align__(16) __half g_vt[32][NROWS];       // [dim-ish][key] f16
__device__ __align__(16) __half g_w1p[2 * 4 * 2048 * 8];  // per-layer W1 repack
__device__ __align__(16) __half g_w2p[2 * 32 * 2048];     // per-layer W2t repack
__device__ __align__(16) __half g_w4p[16 * 4 * 256 * 8];  // fc4 repack [kstep][arr][o][8]
__device__ float g_sizef[NROWS];
__device__ float g_qn[NROWS];
__device__ float g_kmaxpart[128];

// ---- helpers ----
__device__ __forceinline__ u64 f2u(float2 v) { union { float2 f; u64 u; } c; c.f = v; return c.u; }
__device__ __forceinline__ float2 u2f(u64 u) { union { float2 f; u64 u; } c; c.u = u; return c.f; }
__device__ __forceinline__ u64 pack2(float lo, float hi) { float2 v; v.x = lo; v.y = hi; return f2u(v); }
__device__ __forceinline__ u64 fma2(u64 a, u64 b, u64 c) {
    u64 d; asm("fma.rn.f32x2 %0,%1,%2,%3;" : "=l"(d) : "l"(a), "l"(b), "l"(c)); return d;
}
__device__ __forceinline__ float ex2f(float x) {
    float y; asm("ex2.approx.f32 %0,%1;" : "=f"(y) : "f"(x)); return y;
}
__device__ __forceinline__ float wsum(float v) {
#pragma unroll
    for (int o = 16; o; o >>= 1) v += __shfl_xor_sync(0xffffffffu, v, o);
    return v;
}
__device__ __forceinline__ float wmax(float v) {
#pragma unroll
    for (int o = 16; o; o >>= 1) v = fmaxf(v, __shfl_xor_sync(0xffffffffu, v, o));
    return v;
}
__device__ __forceinline__ void cp16(uint32_t dst, const void* src) {
    asm volatile("cp.async.cg.shared.global [%0], [%1], 16;" :: "r"(dst), "l"(src));
}
#define CP_COMMIT() asm volatile("cp.async.commit_group;")
#define CP_WAIT(N)  asm volatile("cp.async.wait_group %0;" :: "n"(N))

__device__ __forceinline__ uint32_t h2pack(float a, float b) {
    __half2 h = __floats2half2_rn(a, b);
    return *(uint32_t*)&h;
}
__device__ __forceinline__ void mma16816(float* d, const uint32_t* a, const uint32_t* b, const float* c) {
    asm volatile(
        "mma.sync.aligned.m16n8k16.row.col.f32.f16.f16.f32 "
        "{%0,%1,%2,%3}, {%4,%5,%6,%7}, {%8,%9}, {%10,%11,%12,%13};"
        : "=f"(d[0]), "=f"(d[1]), "=f"(d[2]), "=f"(d[3])
        : "r"(a[0]), "r"(a[1]), "r"(a[2]), "r"(a[3]), "r"(b[0]), "r"(b[1]),
          "f"(c[0]), "f"(c[1]), "f"(c[2]), "f"(c[3]));
}

// ---------------- fused QKV projection + prep ----------------
#define QS 49
__global__ void __launch_bounds__(256, 1)
qkv_prep_kernel(const float* __restrict__ x0, int use_x,
                const float* __restrict__ W, const float* __restrict__ b) {
    __shared__ float Ws[42 * 14], bs[42], hs[64 * 14], qkvs[64 * QS], sp[2];
    const float* hin = use_x ? x0 : g_h;
    const int t = threadIdx.x;
    const int rb = blockIdx.x * 64;
    for (int i = t; i < 588; i += 256) Ws[i] = W[i];
    if (t < 42) bs[t] = b[t];
    for (int i = t; i < 64 * 14; i += 256) hs[i] = hin[rb * DM + i];
    __syncthreads();
    const float scale = rsqrtf(14.0f) * 1.44269504f;
    for (int idx = t; idx < 64 * 42; idx += 256) {
        int r = idx / 42, c = idx % 42;
        float s = bs[c];
#pragma unroll
        for (int d = 0; d < 14; d++) s = fmaf(hs[r * 14 + d], Ws[c * 14 + d], s);
        qkvs[r * QS + c] = (c < 14) ? s * scale : s;
    }
    __syncthreads();

    if (t < 64) {
        int row = rb + t;
        const float* qr = qkvs + t * QS;
        float qn = 0.f, kn = 0.f;
        float kv[14], vv[14];
#pragma unroll
        for (int d = 0; d < 14; d++) {
            float qf = qr[d];
            g_q[row * DM + d] = qf;
            qn = fmaf(qf, qf, qn);
            kv[d] = qr[14 + d]; kn = fmaf(kv[d], kv[d], kn);
            vv[d] = qr[28 + d];
        }
        g_qn[row] = sqrtf(qn);

        __half hi[16], lo[16];
#pragma unroll
        for (int d = 0; d < 14; d++) {
            hi[d] = __float2half_rn(kv[d]);
            lo[d] = __float2half_rn(kv[d] - __half2float(hi[d]));
        }
        hi[14] = __float2half_rn(1.0f); hi[15] = __float2half_rn(0.f);
        lo[14] = __float2half_rn(0.f);  lo[15] = __float2half_rn(0.f);
        {
            __half* p0 = g_kp + (0 * NROWS + row) * 8;
            __half* p1 = g_kp + (1 * NROWS + row) * 8;
            __half* p2 = g_kp + (2 * NROWS + row) * 8;
            __half* p3 = g_kp + (3 * NROWS + row) * 8;
#pragma unroll
            for (int d = 0; d < 8; d++) { p0[d] = hi[d]; p1[d] = hi[8 + d]; p2[d] = lo[d]; p3[d] = lo[8 + d]; }
        }
#pragma unroll
        for (int d = 0; d < 14; d++) {
            __half vh = __float2half_rn(vv[d]);
            g_vt[d][row] = vh;
            g_vt[16 + d][row] = __float2half_rn(vv[d] - __half2float(vh));
        }
        g_vt[14][row] = __float2half_rn(1.0f);
        g_vt[15][row] = __float2half_rn(0.f);
        g_vt[30][row] = __float2half_rn(0.f);
        g_vt[31][row] = __float2half_rn(0.f);

        kn = wmax(kn);
        if ((t & 31) == 0) sp[t >> 5] = kn;
    }
    __syncthreads();
    if (t == 0) g_kmaxpart[blockIdx.x] = fmaxf(sp[0], sp[1]);
}

// ---------------- mma.sync flash attention, 6-way key split (single wave) -------
#define KBUF 16384
#define BUFSTRIDE (16384 + 16896)
#define ATTN_SMEM (2 * BUFSTRIDE)
__constant__ int c_pstart[NPART + 1] = {0, 6, 12, 17, 22, 27, 32};

__device__ __forceinline__ void tile_cp2(uint32_t sbase, int buf, int key0c, int t) {
    uint32_t dst = sbase + (uint32_t)buf * BUFSTRIDE;
#pragma unroll
    for (int s = 0; s < 4; s++) {
        int i = t + s * 256;
        int a = i >> 8, key = i & 255;
        cp16(dst + (uint32_t)a * 4096 + (uint32_t)key * 16,
             g_kp + ((size_t)a * NROWS + key0c + key) * 8);
    }
#pragma unroll
    for (int s = 0; s < 4; s++) {
        int i = t + s * 256;
        int row = i >> 5, seg = i & 31;
        cp16(dst + KBUF + (uint32_t)row * 528 + (uint32_t)seg * 16,
             &g_vt[row][key0c + seg * 8]);
    }
}

__global__ void __launch_bounds__(256, 3)
attn_mma_kernel() {
    extern __shared__ char smc[];
    const int t = threadIdx.x, lane = t & 31, warp = t >> 5;
    const int g = lane >> 2, tg = lane & 3;
    const int tile = blockIdx.x / NPART, part = blockIdx.x - tile * NPART;
    const int cc0 = c_pstart[part], ccn = c_pstart[part + 1];
    const uint32_t sbase = (uint32_t)__cvta_generic_to_shared(smc);

    float mk2 = 0.f;
    for (int i = lane; i < 128; i += 32) mk2 = fmaxf(mk2, __ldg(g_kmaxpart + i));
    mk2 = wmax(mk2);
    const float maxk = sqrtf(mk2);

    const int qbase = tile * 128 + warp * 16;
    uint32_t qhi[4], qlo[4];
    {
        int r0 = qbase + g, r1 = r0 + 8;
        float v0a = g_q[r0 * DM + 2 * tg],     v1a = g_q[r0 * DM + 2 * tg + 1];
        float v0b = g_q[r1 * DM + 2 * tg],     v1b = g_q[r1 * DM + 2 * tg + 1];
        float v2a, v3a, v2b, v3b;
        if (tg < 3) {
            v2a = g_q[r0 * DM + 8 + 2 * tg]; v3a = g_q[r0 * DM + 9 + 2 * tg];
            v2b = g_q[r1 * DM + 8 + 2 * tg]; v3b = g_q[r1 * DM + 9 + 2 * tg];
        } else {
            v2a = -__ldg(g_qn + r0) * maxk; v3a = 0.f;
            v2b = -__ldg(g_qn + r1) * maxk; v3b = 0.f;
        }
        float vals[4][2] = {{v0a, v1a}, {v0b, v1b}, {v2a, v3a}, {v2b, v3b}};
#pragma unroll
        for (int i = 0; i < 4; i++) {
            qhi[i] = h2pack(vals[i][0], vals[i][1]);
            __half2 hh = *(__half2*)&qhi[i];
            qlo[i] = h2pack(vals[i][0] - __low2float(hh), vals[i][1] - __high2float(hh));
        }
    }

    float O0[4] = {0.f, 0.f, 0.f, 0.f};
    float O1[4] = {0.f, 0.f, 0.f, 0.f};

    tile_cp2(sbase, 0, cc0 * 256, t);
    CP_COMMIT();

    for (int c = cc0; c < ccn; c++) {
        const int cb = c - cc0;
        if (c < ccn - 1) {
            tile_cp2(sbase, (cb + 1) & 1, (c + 1) * 256, t);
            CP_COMMIT();
            CP_WAIT(1);
        } else {
            CP_WAIT(0);
        }
        __syncthreads();

        const char* kb = smc + (cb & 1) * BUFSTRIDE;
        const char* vb = kb + KBUF;

#pragma unroll
        for (int j = 0; j < 256; j += 16) {
            const char* k0 = kb + (size_t)(j + g) * 16 + tg * 4;
            const char* k1 = kb + (size_t)(j + 8 + g) * 16 + tg * 4;
            uint32_t bh0[2] = { *(const uint32_t*)k0,          *(const uint32_t*)(k0 + 4096) };
            uint32_t bl0[2] = { *(const uint32_t*)(k0 + 8192), *(const uint32_t*)(k0 + 12288) };
            uint32_t bh1[2] = { *(const uint32_t*)k1,          *(const uint32_t*)(k1 + 4096) };
            uint32_t bl1[2] = { *(const uint32_t*)(k1 + 8192), *(const uint32_t*)(k1 + 12288) };

            float S0[4] = {0.f, 0.f, 0.f, 0.f}, S1[4] = {0.f, 0.f, 0.f, 0.f};
            mma16816(S0, qhi, bh0, S0);
            mma16816(S0, qhi, bl0, S0);
            mma16816(S0, qlo, bh0, S0);
            mma16816(S1, qhi, bh1, S1);
            mma16816(S1, qhi, bl1, S1);
            mma16816(S1, qlo, bh1, S1);

            // P in f16 hi only; l (ones row in V_hi) uses the SAME phi, so the
            // weight-rounding error cancels in o/l. V_lo MMA kept (value error).
            uint32_t phi[4];
#pragma unroll
            for (int i = 0; i < 4; i++)
                phi[i] = h2pack(ex2f((i < 2) ? S0[2 * i] : S1[2 * (i - 2)]),
                                ex2f((i < 2) ? S0[2 * i + 1] : S1[2 * (i - 2) + 1]));

            const char* v0 = vb + (size_t)(j * 2 + tg * 4);
            uint32_t vh0[2] = { *(const uint32_t*)(v0 + (size_t)g * 528),
                                *(const uint32_t*)(v0 + (size_t)g * 528 + 16) };
            uint32_t vh1[2] = { *(const uint32_t*)(v0 + (size_t)(8 + g) * 528),
                                *(const uint32_t*)(v0 + (size_t)(8 + g) * 528 + 16) };
            uint32_t vl0[2] = { *(const uint32_t*)(v0 + (size_t)(16 + g) * 528),
                                *(const uint32_t*)(v0 + (size_t)(16 + g) * 528 + 16) };
            uint32_t vl1[2] = { *(const uint32_t*)(v0 + (size_t)(24 + g) * 528),
                                *(const uint32_t*)(v0 + (size_t)(24 + g) * 528 + 16) };

            mma16816(O0, phi, vh0, O0);
            mma16816(O1, phi, vh1, O1);
            mma16816(O0, phi, vl0, O0);
            mma16816(O1, phi, vl1, O1);
        }
        __syncthreads();
    }

    {
        int r0 = qbase + g;
        float* d0 = g_part + ((size_t)part * NROWS + r0) * 16;
        float* d1 = g_part + ((size_t)part * NROWS + r0 + 8) * 16;
        *(float2*)(d0 + 2 * tg)     = make_float2(O0[0], O0[1]);
        *(float2*)(d0 + 8 + 2 * tg) = make_float2(O1[0], O1[1]);
        *(float2*)(d1 + 2 * tg)     = make_float2(O0[2], O0[3]);
        *(float2*)(d1 + 8 + 2 * tg) = make_float2(O1[2], O1[3]);
    }
}

// ---------------- combine: 8 threads/row, shuffle-distributed ----------------
__global__ void __launch_bounds__(256, 2)
combine_kernel(const float* __restrict__ x0, int use_x,
               const float* __restrict__ Wo, const float* __restrict__ bo,
               const float* __restrict__ lng, const float* __restrict__ lnb) {
    __shared__ float wos[196], bos[14];
    const int t = threadIdx.x, lane = t & 31;
    for (int i = t; i < 196; i += 256) wos[i] = Wo[i];
    if (t < 14) bos[t] = bo[t];
    __syncthreads();
    const float* hin = use_x ? x0 : g_h;
    const int row = blockIdx.x * 32 + (t >> 3);
    const int e = lane & 7;

    float2 acc = make_float2(0.f, 0.f);
#pragma unroll
    for (int p = 0; p < NPART; p++) {
        float2 v = ((const float2*)(g_part + ((size_t)p * NROWS + row) * 16))[e];
        acc.x += v.x; acc.y += v.y;
    }
    float l = __shfl_sync(0xffffffffu, acc.x, lane | 7);
    float inv = 1.f / l;
    float ax = acc.x * inv, ay = acc.y * inv;
    float a[14];
    const int base = lane & 24;
#pragma unroll
    for (int dp = 0; dp < 7; dp++) {
        a[2 * dp]     = __shfl_sync(0xffffffffu, ax, base + dp);
        a[2 * dp + 1] = __shfl_sync(0xffffffffu, ay, base + dp);
    }
    float pre0 = 0.f, pre1 = 0.f;
    if (e < 7) {
        int d2 = 2 * e;
        pre0 = bos[d2]; pre1 = bos[d2 + 1];
#pragma unroll
        for (int d = 0; d < 14; d++) {
            pre0 = fmaf(a[d], wos[d2 * 14 + d], pre0);
            pre1 = fmaf(a[d], wos[(d2 + 1) * 14 + d], pre1);
        }
        pre0 += hin[row * DM + d2];
        pre1 += hin[row * DM + d2 + 1];
    }
    float s = pre0 + pre1;
#pragma unroll
    for (int o = 4; o; o >>= 1) s += __shfl_xor_sync(0xffffffffu, s, o);
    float mu = s * (1.f / 14.f);
    float z0 = (e < 7) ? pre0 - mu : 0.f;
    float z1 = (e < 7) ? pre1 - mu : 0.f;
    float v = z0 * z0 + z1 * z1;
#pragma unroll
    for (int o = 4; o; o >>= 1) v += __shfl_xor_sync(0xffffffffu, v, o);
    float rs = rsqrtf(v * (1.f / 14.f) + EPS);
    if (e < 7) {
        int d2 = 2 * e;
        g_h[row * DM + d2]     = z0 * rs * __ldg(lng + d2)     + __ldg(lnb + d2);
        g_h[row * DM + d2 + 1] = z1 * rs * __ldg(lng + d2 + 1) + __ldg(lnb + d2 + 1);
    }
}

// ---------------- wprep (FFN weights, both layers, once) ----------------
__global__ void __launch_bounds__(256, 1)
wprep_all_kernel(const float* __restrict__ W1a, const float* __restrict__ b1a,
                 const float* __restrict__ W2a) {
    int idx = blockIdx.x * 256 + threadIdx.x;
    int layer = idx >> 11, j = idx & 2047;
    const float* W1 = W1a + layer * 28672;
    const float* b1 = b1a + layer * 2048;
    const float* W2 = W2a + layer * 28672;
    __half* w1p = g_w1p + layer * 65536;
    __half* w2p = g_w2p + layer * 65536;

    __half hi[16], lo[16];
#pragma unroll
    for (int d = 0; d < 14; d++) {
        float w = W1[j * 14 + d];
        hi[d] = __float2half_rn(w);
        lo[d] = __float2half_rn(w - __half2float(hi[d]));
    }
    {
        float bb = __ldg(b1 + j);
        hi[14] = __float2half_rn(bb);
        lo[14] = __float2half_rn(bb - __half2float(hi[14]));
        hi[15] = __float2half_rn(0.f); lo[15] = __float2half_rn(0.f);
    }
    {
        __half* p0 = w1p + (0 * 2048 + j) * 8;
        __half* p1 = w1p + (1 * 2048 + j) * 8;
        __half* p2 = w1p + (2 * 2048 + j) * 8;
        __half* p3 = w1p + (3 * 2048 + j) * 8;
#pragma unroll
        for (int d = 0; d < 8; d++) { p0[d] = hi[d]; p1[d] = hi[8 + d]; p2[d] = lo[d]; p3[d] = lo[8 + d]; }
    }
#pragma unroll
    for (int d = 0; d < 14; d++) {
        float w = W2[d * 2048 + j];
        __half wh = __float2half_rn(w);
        w2p[d * 2048 + j] = wh;
        w2p[(16 + d) * 2048 + j] = __float2half_rn(w - __half2float(wh));
    }
    w2p[14 * 2048 + j] = __float2half_rn(0.f);
    w2p[15 * 2048 + j] = __float2half_rn(0.f);
    w2p[30 * 2048 + j] = __float2half_rn(0.f);
    w2p[31 * 2048 + j] = __float2half_rn(0.f);
}

// ---------------- wprep4 (fc4 repack, once) ----------------
__global__ void __launch_bounds__(256, 1)
wprep4_kernel(const float* __restrict__ w4) {
    int idx = blockIdx.x * 256 + threadIdx.x;
    int kstep = idx >> 8, o = idx & 255;
#pragma unroll
    for (int e = 0; e < 8; e++) {
        float wa = w4[o * 256 + kstep * 16 + e];
        float wb = w4[o * 256 + kstep * 16 + 8 + e];
        __half ha = __float2half_rn(wa);
        __half hb = __float2half_rn(wb);
        g_w4p[((kstep * 4 + 0) * 256 + o) * 8 + e] = ha;
        g_w4p[((kstep * 4 + 1) * 256 + o) * 8 + e] = hb;
        g_w4p[((kstep * 4 + 2) * 256 + o) * 8 + e] = __float2half_rn(wa - __half2float(ha));
        g_w4p[((kstep * 4 + 3) * 256 + o) * 8 + e] = __float2half_rn(wb - __half2float(hb));
    }
}

// ---------------- FFN via mma.sync (+fused head1 on layer 1) ----------------
#define FW1B 16384
#define FBUF (FW1B + 16896)
#define FFN_SMEM (2 * FBUF)
__device__ __forceinline__ void ffn_cp(uint32_t sbase, int buf, int chunk, int t, int layer) {
    uint32_t dst = sbase + (uint32_t)buf * FBUF;
    const __half* w1p = g_w1p + layer * 65536;
    const __half* w2p = g_w2p + layer * 65536;
#pragma unroll
    for (int s = 0; s < 4; s++) {
        int i = t + s * 256;
        int a = i >> 8, j = i & 255;
        cp16(dst + (uint32_t)a * 4096 + (uint32_t)j * 16,
             w1p + ((size_t)a * 2048 + chunk * 256 + j) * 8);
    }
#pragma unroll
    for (int s = 0; s < 4; s++) {
        int i = t + s * 256;
        int row = i >> 5, seg = i & 31;
        cp16(dst + FW1B + (uint32_t)row * 528 + (uint32_t)seg * 16,
             w2p + (size_t)row * 2048 + chunk * 256 + seg * 8);
    }
}

__global__ void __launch_bounds__(256, 2)
ffn_mma_kernel(int layer, const float* __restrict__ b2,
               const float* __restrict__ lng, const float* __restrict__ lnb,
               const float* __restrict__ fc1w, const float* __restrict__ fc1b,
               const float* __restrict__ fc2w, const float* __restrict__ fc2b,
               float* __restrict__ out) {
    extern __shared__ char smc[];
    const int t = threadIdx.x, lane = t & 31, warp = t >> 5;
    const int g = lane >> 2, tg = lane & 3;
    const int rw = warp & 1, jq = warp >> 1;
    const uint32_t sbase = (uint32_t)__cvta_generic_to_shared(smc);
    const int rbase = blockIdx.x * 32 + rw * 16;

    uint32_t qhi[4], qlo[4];
    {
        int r0 = rbase + g, r1 = r0 + 8;
        float v0a = g_h[r0 * DM + 2 * tg],     v1a = g_h[r0 * DM + 2 * tg + 1];
        float v0b = g_h[r1 * DM + 2 * tg],     v1b = g_h[r1 * DM + 2 * tg + 1];
        float v2a, v3a, v2b, v3b;
        if (tg < 3) {
            v2a = g_h[r0 * DM + 8 + 2 * tg]; v3a = g_h[r0 * DM + 9 + 2 * tg];
            v2b = g_h[r1 * DM + 8 + 2 * tg]; v3b = g_h[r1 * DM + 9 + 2 * tg];
        } else {
            v2a = 1.0f; v3a = 0.f;
            v2b = 1.0f; v3b = 0.f;
        }
        float vals[4][2] = {{v0a, v1a}, {v0b, v1b}, {v2a, v3a}, {v2b, v3b}};
#pragma unroll
        for (int i = 0; i < 4; i++) {
            qhi[i] = h2pack(vals[i][0], vals[i][1]);
            __half2 hh = *(__half2*)&qhi[i];
            qlo[i] = h2pack(vals[i][0] - __low2float(hh), vals[i][1] - __high2float(hh));
        }
    }

    float O0[4] = {0.f, 0.f, 0.f, 0.f};
    float O1[4] = {0.f, 0.f, 0.f, 0.f};

    ffn_cp(sbase, 0, 0, t, layer);
    CP_COMMIT();

    for (int c = 0; c < 8; c++) {
        if (c < 7) {
            ffn_cp(sbase, (c + 1) & 1, c + 1, t, layer);
            CP_COMMIT();
            CP_WAIT(1);
        } else {
            CP_WAIT(0);
        }
        __syncthreads();

        const char* kb = smc + (c & 1) * FBUF;
        const char* vb = kb + FW1B;

        for (int step = 0; step < 4; step++) {
            const int j = jq * 64 + step * 16;
            const char* k0 = kb + (size_t)(j + g) * 16 + tg * 4;
            const char* k1 = kb + (size_t)(j + 8 + g) * 16 + tg * 4;
            uint32_t bh0[2] = { *(const uint32_t*)k0,          *(const uint32_t*)(k0 + 4096) };
            uint32_t bl0[2] = { *(const uint32_t*)(k0 + 8192), *(const uint32_t*)(k0 + 12288) };
            uint32_t bh1[2] = { *(const uint32_t*)k1,          *(const uint32_t*)(k1 + 4096) };
            uint32_t bl1[2] = { *(const uint32_t*)(k1 + 8192), *(const uint32_t*)(k1 + 12288) };

            float S0[4] = {0.f, 0.f, 0.f, 0.f}, S1[4] = {0.f, 0.f, 0.f, 0.f};
            mma16816(S0, qhi, bh0, S0);
            mma16816(S0, qhi, bl0, S0);
            mma16816(S0, qlo, bh0, S0);
            mma16816(S1, qhi, bh1, S1);
            mma16816(S1, qhi, bl1, S1);
            mma16816(S1, qlo, bh1, S1);

            float p[8];
#pragma unroll
            for (int i = 0; i < 4; i++) { p[i] = fmaxf(S0[i], 0.f); p[4 + i] = fmaxf(S1[i], 0.f); }
            uint32_t phi[4], plo[4];
#pragma unroll
            for (int i = 0; i < 4; i++) {
                phi[i] = h2pack(p[2 * i], p[2 * i + 1]);
                __half2 hh = *(__half2*)&phi[i];
                plo[i] = h2pack(p[2 * i] - __low2float(hh), p[2 * i + 1] - __high2float(hh));
            }

            const char* v0 = vb + (size_t)(j * 2 + tg * 4);
            uint32_t vh0[2] = { *(const uint32_t*)(v0 + (size_t)g * 528),
                                *(const uint32_t*)(v0 + (size_t)g * 528 + 16) };
            uint32_t vh1[2] = { *(const uint32_t*)(v0 + (size_t)(8 + g) * 528),
                                *(const uint32_t*)(v0 + (size_t)(8 + g) * 528 + 16) };
            uint32_t vl0[2] = { *(const uint32_t*)(v0 + (size_t)(16 + g) * 528),
                                *(const uint32_t*)(v0 + (size_t)(16 + g) * 528 + 16) };
            uint32_t vl1[2] = { *(const uint32_t*)(v0 + (size_t)(24 + g) * 528),
                                *(const uint32_t*)(v0 + (size_t)(24 + g) * 528 + 16) };

            mma16816(O0, phi, vh0, O0);
            mma16816(O1, phi, vh1, O1);
            mma16816(O0, plo, vh0, O0);
            mma16816(O1, plo, vh1, O1);
            mma16816(O0, phi, vl0, O0);
            mma16816(O1, phi, vl1, O1);
        }
        __syncthreads();
    }

    {
        float* osum = (float*)smc;
        int lr = rw * 16 + g;
        float* om = osum + jq * 512;
        om[lr * 16 + 2 * tg]           = O0[0];
        om[lr * 16 + 2 * tg + 1]       = O0[1];
        om[lr * 16 + 8 + 2 * tg]       = O1[0];
        om[lr * 16 + 9 + 2 * tg]       = O1[1];
        om[(lr + 8) * 16 + 2 * tg]     = O0[2];
        om[(lr + 8) * 16 + 2 * tg + 1] = O0[3];
        om[(lr + 8) * 16 + 8 + 2 * tg] = O1[2];
        om[(lr + 8) * 16 + 9 + 2 * tg] = O1[3];
        __syncthreads();
        if (t < 32) {
            int row = blockIdx.x * 32 + t;
            float pre[14], mu = 0.f;
#pragma unroll
            for (int d = 0; d < 14; d++) {
                float v = osum[t * 16 + d] + osum[512 + t * 16 + d]
                        + osum[1024 + t * 16 + d] + osum[1536 + t * 16 + d]
                        + __ldg(b2 + d) + g_h[row * DM + d];
                pre[d] = v; mu += v;
            }
            mu *= (1.f / 14.f);
            float var = 0.f;
#pragma unroll
            for (int d = 0; d < 14; d++) { float z = pre[d] - mu; var = fmaf(z, z, var); }
            float rs = rsqrtf(var * (1.f / 14.f) + EPS);
            float hv[14];
#pragma unroll
            for (int d = 0; d < 14; d++) {
                hv[d] = (pre[d] - mu) * rs * __ldg(lng + d) + __ldg(lnb + d);
                g_h[row * DM + d] = hv[d];
            }
            if (layer == 1) {
                float size = __ldg(fc2b);
#pragma unroll
                for (int d2 = 0; d2 < 14; d2++) {
                    float s = __ldg(fc1b + d2);
#pragma unroll
                    for (int d = 0; d < 14; d++) s = fmaf(hv[d], __ldg(fc1w + d2 * 14 + d), s);
                    size = fmaf(s, __ldg(fc2w + d2), size);
                }
                out[row] = size;
                g_sizef[row] = (float)(int)size;
            }
        }
    }
}

// ---------------- head2 via mma.sync ----------------
#define H2WB 16384
#define H2_INS   (2 * H2WB)
#define H2_R1H   (H2_INS + 1632 * 4)
#define H2_R1L   (H2_R1H + 32 * 264 * 2)
#define H2_RED   (H2_R1L + 32 * 264 * 2)
#define H2_SMEM  (H2_RED + 128 * 4)
__device__ __forceinline__ void h2cp(uint32_t sbase, int buf, int kstep, int t) {
    uint32_t dst = sbase + (uint32_t)buf * H2WB;
    const __half* src = g_w4p + (size_t)kstep * 8192;
#pragma unroll
    for (int s = 0; s < 4; s++) {
        int i = t + s * 256;
        cp16(dst + (uint32_t)i * 16, src + (size_t)i * 8);
    }
}

__global__ void __launch_bounds__(256, 2)
head2_mma_kernel(const float* __restrict__ x, const float* __restrict__ y,
                 const float* __restrict__ w3, const float* __restrict__ b3,
                 const float* __restrict__ b4,
                 const float* __restrict__ w5, const float* __restrict__ b5,
                 float* __restrict__ out) {
    extern __shared__ char smc[];
    float*  ins = (float*)(smc + H2_INS);
    __half* r1h = (__half*)(smc + H2_R1H);
    __half* r1l = (__half*)(smc + H2_R1L);
    float*  red = (float*)(smc + H2_RED);
    const int t = threadIdx.x, lane = t & 31, warp = t >> 5;
    const int g = lane >> 2, tg = lane & 3;
    const int rw = warp & 1, nq = warp >> 1;
    const uint32_t sbase = (uint32_t)__cvta_generic_to_shared(smc);
    const int rbase = blockIdx.x * 32;

    h2cp(sbase, 0, 0, t);
    CP_COMMIT();
    h2cp(sbase, 1, 1, t);
    CP_COMMIT();

    for (int i = t; i < 32 * 51; i += 256) {
        int r = i / 51, c = i % 51, row = rbase + r;
        float v;
        if (c == 0)      v = g_sizef[row];
        else if (c < 15) v = x[row * DM + c - 1];
        else             v = y[row * MF + c - 15];
        ins[i] = v;
    }
    __syncthreads();

    {
        float r1a[32];
        float b3t = __ldg(b3 + t);
#pragma unroll
        for (int r = 0; r < 32; r++) r1a[r] = b3t;
        const float* w3r = w3 + t * 51;
        for (int i = 0; i < 51; i++) {
            float w = __ldg(w3r + i);
#pragma unroll
            for (int r = 0; r < 32; r++) r1a[r] = fmaf(ins[r * 51 + i], w, r1a[r]);
        }
#pragma unroll
        for (int r = 0; r < 32; r++) {
            float v = fmaxf(r1a[r], 0.f);
            __half h = __float2half_rn(v);
            r1h[r * 264 + t] = h;
            r1l[r * 264 + t] = __float2half_rn(v - __half2float(h));
        }
    }
    __syncthreads();

    float O[8][4];
#pragma unroll
    for (int nt = 0; nt < 8; nt++)
#pragma unroll
        for (int i = 0; i < 4; i++) O[nt][i] = 0.f;

    const int r0 = rw * 16 + g;
    for (int kstep = 0; kstep < 16; kstep++) {
        CP_WAIT(1);
        __syncthreads();

        const int kb2 = kstep * 16 + 2 * tg;
        uint32_t ahi[4], alo[4];
        ahi[0] = *(const uint32_t*)&r1h[r0 * 264 + kb2];
        ahi[1] = *(const uint32_t*)&r1h[(r0 + 8) * 264 + kb2];
        ahi[2] = *(const uint32_t*)&r1h[r0 * 264 + kb2 + 8];
        ahi[3] = *(const uint32_t*)&r1h[(r0 + 8) * 264 + kb2 + 8];
        alo[0] = *(const uint32_t*)&r1l[r0 * 264 + kb2];
        alo[1] = *(const uint32_t*)&r1l[(r0 + 8) * 264 + kb2];
        alo[2] = *(const uint32_t*)&r1l[r0 * 264 + kb2 + 8];
        alo[3] = *(const uint32_t*)&r1l[(r0 + 8) * 264 + kb2 + 8];

        const char* wb = smc + (kstep & 1) * H2WB;
#pragma unroll
        for (int nt = 0; nt < 8; nt++) {
            int o0 = nq * 64 + nt * 8;
            const char* p = wb + (size_t)(o0 + g) * 16 + tg * 4;
            uint32_t bh[2] = { *(const uint32_t*)p,          *(const uint32_t*)(p + 4096) };
            uint32_t bl[2] = { *(const uint32_t*)(p + 8192), *(const uint32_t*)(p + 12288) };
            mma16816(O[nt], ahi, bh, O[nt]);
            mma16816(O[nt], ahi, bl, O[nt]);
            mma16816(O[nt], alo, bh, O[nt]);
        }
        __syncthreads();
        if (kstep + 2 < 16) {
            h2cp(sbase, kstep & 1, kstep + 2, t);
            CP_COMMIT();
        }
    }

    float s0 = 0.f, s1 = 0.f;
#pragma unroll
    for (int nt = 0; nt < 8; nt++) {
        int o = nq * 64 + nt * 8 + 2 * tg;
        float b4a = __ldg(b4 + o),     b4b = __ldg(b4 + o + 1);
        float w5a = __ldg(w5 + o),     w5b = __ldg(w5 + o + 1);
        s0 += fmaxf(O[nt][0] + b4a, 0.f) * w5a + fmaxf(O[nt][1] + b4b, 0.f) * w5b;
        s1 += fmaxf(O[nt][2] + b4a, 0.f) * w5a + fmaxf(O[nt][3] + b4b, 0.f) * w5b;
    }
    s0 += __shfl_xor_sync(0xffffffffu, s0, 1); s0 += __shfl_xor_sync(0xffffffffu, s0, 2);
    s1 += __shfl_xor_sync(0xffffffffu, s1, 1); s1 += __shfl_xor_sync(0xffffffffu, s1, 2);
    if (tg == 0) {
        red[nq * 32 + r0] = s0;
        red[nq * 32 + r0 + 8] = s1;
    }
    __syncthreads();
    if (t < 32) {
        int row = rbase + t;
        float s = __ldg(b5) + red[t] + red[32 + t] + red[64 + t] + red[96 + t];
        out[NROWS + row] = (g_sizef[row] != 0.f) ? s : 0.f;
    }
}

// ---------------- launcher ----------------
extern "C" void kernel_launch(void* const* d_in, const int* in_sizes, int n_in,
                              void* d_out, int out_size) {
    const float* x    = (const float*)d_in[0];
    const float* y    = (const float*)d_in[1];
    const float* wqkv = (const float*)d_in[2];
    const float* bqkv = (const float*)d_in[3];
    const float* wo   = (const float*)d_in[4];
    const float* bo   = (const float*)d_in[5];
    const float* ln1g = (const float*)d_in[6];
    const float* ln1b = (const float*)d_in[7];
    const float* ffw1 = (const float*)d_in[8];
    const float* ffb1 = (const float*)d_in[9];
    const float* ffw2 = (const float*)d_in[10];
    const float* ffb2 = (const float*)d_in[11];
    const float* ln2g = (const float*)d_in[12];
    const float* ln2b = (const float*)d_in[13];
    const float* fc1w = (const float*)d_in[14];
    const float* fc1b = (const float*)d_in[15];
    const float* fc2w = (const float*)d_in[16];
    const float* fc2b = (const float*)d_in[17];
    const float* fc3w = (const float*)d_in[18];
    const float* fc3b = (const float*)d_in[19];
    const float* fc4w = (const float*)d_in[20];
    const float* fc4b = (const float*)d_in[21];
    const float* fc5w = (const float*)d_in[22];
    const float* fc5b = (const float*)d_in[23];
    float* out = (float*)d_out;

    cudaFuncSetAttribute(attn_mma_kernel,  cudaFuncAttributeMaxDynamicSharedMemorySize, ATTN_SMEM);
    cudaFuncSetAttribute(ffn_mma_kernel,   cudaFuncAttributeMaxDynamicSharedMemorySize, FFN_SMEM);
    cudaFuncSetAttribute(head2_mma_kernel, cudaFuncAttributeMaxDynamicSharedMemorySize, H2_SMEM);

    wprep_all_kernel<<<16, 256>>>(ffw1, ffb1, ffw2);
    wprep4_kernel<<<16, 256>>>(fc4w);
    for (int l = 0; l < 2; l++) {
        qkv_prep_kernel<<<128, 256>>>(x, (l == 0) ? 1 : 0, wqkv + l * 588, bqkv + l * 42);
        attn_mma_kernel<<<64 * NPART, 256, ATTN_SMEM>>>();
        combine_kernel<<<256, 256>>>(x, (l == 0) ? 1 : 0, wo + l * 196, bo + l * 14,
                                     ln1g + l * 14, ln1b + l * 14);
        ffn_mma_kernel<<<256, 256, FFN_SMEM>>>(l, ffb2 + l * 14, ln2g + l * 14, ln2b + l * 14,
                                               fc1w, fc1b, fc2w, fc2b, out);
    }
    head2_mma_kernel<<<256, 256, H2_SMEM>>>(x, y, fc3w, fc3b, fc4b, fc5w, fc5b, out);
}

// round 16
// speedup vs baseline: 1.5174x; 1.0288x over previous
#include <cuda_runtime.h>
#include <cuda_fp16.h>
#include <stdint.h>

#define NROWS 8192
#define DM 14
#define MF 36
#define EPS 1e-5f
#define NPART 6
typedef unsigned long long u64;

__device__ __align__(16) float g_h[NROWS * DM];
__device__ __align__(16) float g_q[NROWS * DM];   // pre-scaled by D^-0.5*log2(e)
__device__ __align__(16) float g_part[NPART * NROWS * 16];
__device__ __align__(16) __half g_kp[4 * NROWS * 8];   // [arr][key][8] f16
__device__ __align__(16) __half g_vt[32][NROWS];       // [dim-ish][key] f16
__device__ __align__(16) __half g_w1p[2 * 4 * 2048 * 8];  // per-layer W1 repack
__device__ __align__(16) __half g_w2p[2 * 32 * 2048];     // per-layer W2t repack
__device__ __align__(16) __half g_w4p[16 * 4 * 256 * 8];  // fc4 repack [kstep][arr][o][8]
__device__ float g_sizef[NROWS];
__device__ float g_qn[NROWS];
__device__ float g_kmaxpart[128];

// ---- helpers ----
__device__ __forceinline__ u64 f2u(float2 v) { union { float2 f; u64 u; } c; c.f = v; return c.u; }
__device__ __forceinline__ float2 u2f(u64 u) { union { float2 f; u64 u; } c; c.u = u; return c.f; }
__device__ __forceinline__ u64 pack2(float lo, float hi) { float2 v; v.x = lo; v.y = hi; return f2u(v); }
__device__ __forceinline__ u64 fma2(u64 a, u64 b, u64 c) {
    u64 d; asm("fma.rn.f32x2 %0,%1,%2,%3;" : "=l"(d) : "l"(a), "l"(b), "l"(c)); return d;
}
__device__ __forceinline__ float ex2f(float x) {
    float y; asm("ex2.approx.f32 %0,%1;" : "=f"(y) : "f"(x)); return y;
}
__device__ __forceinline__ float wsum(float v) {
#pragma unroll
    for (int o = 16; o; o >>= 1) v += __shfl_xor_sync(0xffffffffu, v, o);
    return v;
}
__device__ __forceinline__ float wmax(float v) {
#pragma unroll
    for (int o = 16; o; o >>= 1) v = fmaxf(v, __shfl_xor_sync(0xffffffffu, v, o));
    return v;
}
__device__ __forceinline__ void cp16(uint32_t dst, const void* src) {
    asm volatile("cp.async.cg.shared.global [%0], [%1], 16;" :: "r"(dst), "l"(src));
}
#define CP_COMMIT() asm volatile("cp.async.commit_group;")
#define CP_WAIT(N)  asm volatile("cp.async.wait_group %0;" :: "n"(N))

__device__ __forceinline__ uint32_t h2pack(float a, float b) {
    __half2 h = __floats2half2_rn(a, b);
    return *(uint32_t*)&h;
}
__device__ __forceinline__ void mma16816(float* d, const uint32_t* a, const uint32_t* b, const float* c) {
    asm volatile(
        "mma.sync.aligned.m16n8k16.row.col.f32.f16.f16.f32 "
        "{%0,%1,%2,%3}, {%4,%5,%6,%7}, {%8,%9}, {%10,%11,%12,%13};"
        : "=f"(d[0]), "=f"(d[1]), "=f"(d[2]), "=f"(d[3])
        : "r"(a[0]), "r"(a[1]), "r"(a[2]), "r"(a[3]), "r"(b[0]), "r"(b[1]),
          "f"(c[0]), "f"(c[1]), "f"(c[2]), "f"(c[3]));
}
__device__ __forceinline__ void ldsm4(uint32_t* r, uint32_t addr) {
    asm volatile("ldmatrix.sync.aligned.m8n8.x4.shared.b16 {%0,%1,%2,%3}, [%4];"
        : "=r"(r[0]), "=r"(r[1]), "=r"(r[2]), "=r"(r[3]) : "r"(addr));
}

// ---------------- fused QKV projection + prep ----------------
#define QS 49
__global__ void __launch_bounds__(256, 1)
qkv_prep_kernel(const float* __restrict__ x0, int use_x,
                const float* __restrict__ W, const float* __restrict__ b) {
    __shared__ float Ws[42 * 14], bs[42], hs[64 * 14], qkvs[64 * QS], sp[2];
    const float* hin = use_x ? x0 : g_h;
    const int t = threadIdx.x;
    const int rb = blockIdx.x * 64;
    for (int i = t; i < 588; i += 256) Ws[i] = W[i];
    if (t < 42) bs[t] = b[t];
    for (int i = t; i < 64 * 14; i += 256) hs[i] = hin[rb * DM + i];
    __syncthreads();
    const float scale = rsqrtf(14.0f) * 1.44269504f;
    for (int idx = t; idx < 64 * 42; idx += 256) {
        int r = idx / 42, c = idx % 42;
        float s = bs[c];
#pragma unroll
        for (int d = 0; d < 14; d++) s = fmaf(hs[r * 14 + d], Ws[c * 14 + d], s);
        qkvs[r * QS + c] = (c < 14) ? s * scale : s;
    }
    __syncthreads();

    if (t < 64) {
        int row = rb + t;
        const float* qr = qkvs + t * QS;
        float qn = 0.f, kn = 0.f;
        float kv[14], vv[14];
#pragma unroll
        for (int d = 0; d < 14; d++) {
            float qf = qr[d];
            g_q[row * DM + d] = qf;
            qn = fmaf(qf, qf, qn);
            kv[d] = qr[14 + d]; kn = fmaf(kv[d], kv[d], kn);
            vv[d] = qr[28 + d];
        }
        g_qn[row] = sqrtf(qn);

        __half hi[16], lo[16];
#pragma unroll
        for (int d = 0; d < 14; d++) {
            hi[d] = __float2half_rn(kv[d]);
            lo[d] = __float2half_rn(kv[d] - __half2float(hi[d]));
        }
        hi[14] = __float2half_rn(1.0f); hi[15] = __float2half_rn(0.f);
        lo[14] = __float2half_rn(0.f);  lo[15] = __float2half_rn(0.f);
        {
            __half* p0 = g_kp + (0 * NROWS + row) * 8;
            __half* p1 = g_kp + (1 * NROWS + row) * 8;
            __half* p2 = g_kp + (2 * NROWS + row) * 8;
            __half* p3 = g_kp + (3 * NROWS + row) * 8;
#pragma unroll
            for (int d = 0; d < 8; d++) { p0[d] = hi[d]; p1[d] = hi[8 + d]; p2[d] = lo[d]; p3[d] = lo[8 + d]; }
        }
#pragma unroll
        for (int d = 0; d < 14; d++) {
            __half vh = __float2half_rn(vv[d]);
            g_vt[d][row] = vh;
            g_vt[16 + d][row] = __float2half_rn(vv[d] - __half2float(vh));
        }
        g_vt[14][row] = __float2half_rn(1.0f);
        g_vt[15][row] = __float2half_rn(0.f);
        g_vt[30][row] = __float2half_rn(0.f);
        g_vt[31][row] = __float2half_rn(0.f);

        kn = wmax(kn);
        if ((t & 31) == 0) sp[t >> 5] = kn;
    }
    __syncthreads();
    if (t == 0) g_kmaxpart[blockIdx.x] = fmaxf(sp[0], sp[1]);
}

// ---------------- mma.sync flash attention, 6-way key split (single wave) -------
#define KBUF 16384
#define BUFSTRIDE (16384 + 16896)
#define ATTN_SMEM (2 * BUFSTRIDE)
__constant__ int c_pstart[NPART + 1] = {0, 6, 12, 17, 22, 27, 32};

__device__ __forceinline__ void tile_cp2(uint32_t sbase, int buf, int key0c, int t) {
    uint32_t dst = sbase + (uint32_t)buf * BUFSTRIDE;
#pragma unroll
    for (int s = 0; s < 4; s++) {
        int i = t + s * 256;
        int a = i >> 8, key = i & 255;
        cp16(dst + (uint32_t)a * 4096 + (uint32_t)key * 16,
             g_kp + ((size_t)a * NROWS + key0c + key) * 8);
    }
#pragma unroll
    for (int s = 0; s < 4; s++) {
        int i = t + s * 256;
        int row = i >> 5, seg = i & 31;
        cp16(dst + KBUF + (uint32_t)row * 528 + (uint32_t)seg * 16,
             &g_vt[row][key0c + seg * 8]);
    }
}

__global__ void __launch_bounds__(256, 3)
attn_mma_kernel() {
    extern __shared__ char smc[];
    const int t = threadIdx.x, lane = t & 31, warp = t >> 5;
    const int g = lane >> 2, tg = lane & 3;
    const int tile = blockIdx.x / NPART, part = blockIdx.x - tile * NPART;
    const int cc0 = c_pstart[part], ccn = c_pstart[part + 1];
    const uint32_t sbase = (uint32_t)__cvta_generic_to_shared(smc);

    // ldmatrix lane row-offsets (m = matrix idx pair, r = row in matrix)
    const int lm = lane >> 3, lr = lane & 7;
    const uint32_t okh = (uint32_t)((((lm >> 1) * 8 + lr) * 16) + (lm & 1) * 4096);
    const uint32_t ovh = (uint32_t)(lr * 528 + (lm & 1) * 16 + (lm >> 1) * 4224);

    float mk2 = 0.f;
    for (int i = lane; i < 128; i += 32) mk2 = fmaxf(mk2, __ldg(g_kmaxpart + i));
    mk2 = wmax(mk2);
    const float maxk = sqrtf(mk2);

    const int qbase = tile * 128 + warp * 16;
    uint32_t qhi[4], qlo[4];
    {
        int r0 = qbase + g, r1 = r0 + 8;
        float v0a = g_q[r0 * DM + 2 * tg],     v1a = g_q[r0 * DM + 2 * tg + 1];
        float v0b = g_q[r1 * DM + 2 * tg],     v1b = g_q[r1 * DM + 2 * tg + 1];
        float v2a, v3a, v2b, v3b;
        if (tg < 3) {
            v2a = g_q[r0 * DM + 8 + 2 * tg]; v3a = g_q[r0 * DM + 9 + 2 * tg];
            v2b = g_q[r1 * DM + 8 + 2 * tg]; v3b = g_q[r1 * DM + 9 + 2 * tg];
        } else {
            v2a = -__ldg(g_qn + r0) * maxk; v3a = 0.f;
            v2b = -__ldg(g_qn + r1) * maxk; v3b = 0.f;
        }
        float vals[4][2] = {{v0a, v1a}, {v0b, v1b}, {v2a, v3a}, {v2b, v3b}};
#pragma unroll
        for (int i = 0; i < 4; i++) {
            qhi[i] = h2pack(vals[i][0], vals[i][1]);
            __half2 hh = *(__half2*)&qhi[i];
            qlo[i] = h2pack(vals[i][0] - __low2float(hh), vals[i][1] - __high2float(hh));
        }
    }

    float O0[4] = {0.f, 0.f, 0.f, 0.f};
    float O1[4] = {0.f, 0.f, 0.f, 0.f};

    tile_cp2(sbase, 0, cc0 * 256, t);
    CP_COMMIT();

    for (int c = cc0; c < ccn; c++) {
        const int cb = c - cc0;
        if (c < ccn - 1) {
            tile_cp2(sbase, (cb + 1) & 1, (c + 1) * 256, t);
            CP_COMMIT();
            CP_WAIT(1);
        } else {
            CP_WAIT(0);
        }
        __syncthreads();

        uint32_t kaddr = sbase + (uint32_t)(cb & 1) * BUFSTRIDE + okh;
        uint32_t vaddr = sbase + (uint32_t)(cb & 1) * BUFSTRIDE + KBUF + ovh;

#pragma unroll
        for (int j = 0; j < 256; j += 16) {
            uint32_t kh[4], kl[4], vh[4], vl[4];
            ldsm4(kh, kaddr);
            ldsm4(kl, kaddr + 8192);
            ldsm4(vh, vaddr);
            ldsm4(vl, vaddr + 8448);
            kaddr += 256;
            vaddr += 32;

            float S0[4] = {0.f, 0.f, 0.f, 0.f}, S1[4] = {0.f, 0.f, 0.f, 0.f};
            mma16816(S0, qhi, kh,     S0);
            mma16816(S0, qhi, kl,     S0);
            mma16816(S0, qlo, kh,     S0);
            mma16816(S1, qhi, kh + 2, S1);
            mma16816(S1, qhi, kl + 2, S1);
            mma16816(S1, qlo, kh + 2, S1);

            uint32_t phi[4];
#pragma unroll
            for (int i = 0; i < 4; i++)
                phi[i] = h2pack(ex2f((i < 2) ? S0[2 * i] : S1[2 * (i - 2)]),
                                ex2f((i < 2) ? S0[2 * i + 1] : S1[2 * (i - 2) + 1]));

            mma16816(O0, phi, vh,     O0);
            mma16816(O1, phi, vh + 2, O1);
            mma16816(O0, phi, vl,     O0);
            mma16816(O1, phi, vl + 2, O1);
        }
        __syncthreads();
    }

    {
        int r0 = qbase + g;
        float* d0 = g_part + ((size_t)part * NROWS + r0) * 16;
        float* d1 = g_part + ((size_t)part * NROWS + r0 + 8) * 16;
        *(float2*)(d0 + 2 * tg)     = make_float2(O0[0], O0[1]);
        *(float2*)(d0 + 8 + 2 * tg) = make_float2(O1[0], O1[1]);
        *(float2*)(d1 + 2 * tg)     = make_float2(O0[2], O0[3]);
        *(float2*)(d1 + 8 + 2 * tg) = make_float2(O1[2], O1[3]);
    }
}

// ---------------- combine: 8 threads/row, shuffle-distributed ----------------
__global__ void __launch_bounds__(256, 2)
combine_kernel(const float* __restrict__ x0, int use_x,
               const float* __restrict__ Wo, const float* __restrict__ bo,
               const float* __restrict__ lng, const float* __restrict__ lnb) {
    __shared__ float wos[196], bos[14];
    const int t = threadIdx.x, lane = t & 31;
    for (int i = t; i < 196; i += 256) wos[i] = Wo[i];
    if (t < 14) bos[t] = bo[t];
    __syncthreads();
    const float* hin = use_x ? x0 : g_h;
    const int row = blockIdx.x * 32 + (t >> 3);
    const int e = lane & 7;

    float2 acc = make_float2(0.f, 0.f);
#pragma unroll
    for (int p = 0; p < NPART; p++) {
        float2 v = ((const float2*)(g_part + ((size_t)p * NROWS + row) * 16))[e];
        acc.x += v.x; acc.y += v.y;
    }
    float l = __shfl_sync(0xffffffffu, acc.x, lane | 7);
    float inv = 1.f / l;
    float ax = acc.x * inv, ay = acc.y * inv;
    float a[14];
    const int base = lane & 24;
#pragma unroll
    for (int dp = 0; dp < 7; dp++) {
        a[2 * dp]     = __shfl_sync(0xffffffffu, ax, base + dp);
        a[2 * dp + 1] = __shfl_sync(0xffffffffu, ay, base + dp);
    }
    float pre0 = 0.f, pre1 = 0.f;
    if (e < 7) {
        int d2 = 2 * e;
        pre0 = bos[d2]; pre1 = bos[d2 + 1];
#pragma unroll
        for (int d = 0; d < 14; d++) {
            pre0 = fmaf(a[d], wos[d2 * 14 + d], pre0);
            pre1 = fmaf(a[d], wos[(d2 + 1) * 14 + d], pre1);
        }
        pre0 += hin[row * DM + d2];
        pre1 += hin[row * DM + d2 + 1];
    }
    float s = pre0 + pre1;
#pragma unroll
    for (int o = 4; o; o >>= 1) s += __shfl_xor_sync(0xffffffffu, s, o);
    float mu = s * (1.f / 14.f);
    float z0 = (e < 7) ? pre0 - mu : 0.f;
    float z1 = (e < 7) ? pre1 - mu : 0.f;
    float v = z0 * z0 + z1 * z1;
#pragma unroll
    for (int o = 4; o; o >>= 1) v += __shfl_xor_sync(0xffffffffu, v, o);
    float rs = rsqrtf(v * (1.f / 14.f) + EPS);
    if (e < 7) {
        int d2 = 2 * e;
        g_h[row * DM + d2]     = z0 * rs * __ldg(lng + d2)     + __ldg(lnb + d2);
        g_h[row * DM + d2 + 1] = z1 * rs * __ldg(lng + d2 + 1) + __ldg(lnb + d2 + 1);
    }
}

// ---------------- wprep (FFN weights, both layers, once) ----------------
__global__ void __launch_bounds__(256, 1)
wprep_all_kernel(const float* __restrict__ W1a, const float* __restrict__ b1a,
                 const float* __restrict__ W2a) {
    int idx = blockIdx.x * 256 + threadIdx.x;
    int layer = idx >> 11, j = idx & 2047;
    const float* W1 = W1a + layer * 28672;
    const float* b1 = b1a + layer * 2048;
    const float* W2 = W2a + layer * 28672;
    __half* w1p = g_w1p + layer * 65536;
    __half* w2p = g_w2p + layer * 65536;

    __half hi[16], lo[16];
#pragma unroll
    for (int d = 0; d < 14; d++) {
        float w = W1[j * 14 + d];
        hi[d] = __float2half_rn(w);
        lo[d] = __float2half_rn(w - __half2float(hi[d]));
    }
    {
        float bb = __ldg(b1 + j);
        hi[14] = __float2half_rn(bb);
        lo[14] = __float2half_rn(bb - __half2float(hi[14]));
        hi[15] = __float2half_rn(0.f); lo[15] = __float2half_rn(0.f);
    }
    {
        __half* p0 = w1p + (0 * 2048 + j) * 8;
        __half* p1 = w1p + (1 * 2048 + j) * 8;
        __half* p2 = w1p + (2 * 2048 + j) * 8;
        __half* p3 = w1p + (3 * 2048 + j) * 8;
#pragma unroll
        for (int d = 0; d < 8; d++) { p0[d] = hi[d]; p1[d] = hi[8 + d]; p2[d] = lo[d]; p3[d] = lo[8 + d]; }
    }
#pragma unroll
    for (int d = 0; d < 14; d++) {
        float w = W2[d * 2048 + j];
        __half wh = __float2half_rn(w);
        w2p[d * 2048 + j] = wh;
        w2p[(16 + d) * 2048 + j] = __float2half_rn(w - __half2float(wh));
    }
    w2p[14 * 2048 + j] = __float2half_rn(0.f);
    w2p[15 * 2048 + j] = __float2half_rn(0.f);
    w2p[30 * 2048 + j] = __float2half_rn(0.f);
    w2p[31 * 2048 + j] = __float2half_rn(0.f);
}

// ---------------- wprep4 (fc4 repack, once) ----------------
__global__ void __launch_bounds__(256, 1)
wprep4_kernel(const float* __restrict__ w4) {
    int idx = blockIdx.x * 256 + threadIdx.x;
    int kstep = idx >> 8, o = idx & 255;
#pragma unroll
    for (int e = 0; e < 8; e++) {
        float wa = w4[o * 256 + kstep * 16 + e];
        float wb = w4[o * 256 + kstep * 16 + 8 + e];
        __half ha = __float2half_rn(wa);
        __half hb = __float2half_rn(wb);
        g_w4p[((kstep * 4 + 0) * 256 + o) * 8 + e] = ha;
        g_w4p[((kstep * 4 + 1) * 256 + o) * 8 + e] = hb;
        g_w4p[((kstep * 4 + 2) * 256 + o) * 8 + e] = __float2half_rn(wa - __half2float(ha));
        g_w4p[((kstep * 4 + 3) * 256 + o) * 8 + e] = __float2half_rn(wb - __half2float(hb));
    }
}

// ---------------- FFN via mma.sync (+fused head1 on layer 1) ----------------
#define FW1B 16384
#define FBUF (FW1B + 16896)
#define FFN_SMEM (2 * FBUF)
__device__ __forceinline__ void ffn_cp(uint32_t sbase, int buf, int chunk, int t, int layer) {
    uint32_t dst = sbase + (uint32_t)buf * FBUF;
    const __half* w1p = g_w1p + layer * 65536;
    const __half* w2p = g_w2p + layer * 65536;
#pragma unroll
    for (int s = 0; s < 4; s++) {
        int i = t + s * 256;
        int a = i >> 8, j = i & 255;
        cp16(dst + (uint32_t)a * 4096 + (uint32_t)j * 16,
             w1p + ((size_t)a * 2048 + chunk * 256 + j) * 8);
    }
#pragma unroll
    for (int s = 0; s < 4; s++) {
        int i = t + s * 256;
        int row = i >> 5, seg = i & 31;
        cp16(dst + FW1B + (uint32_t)row * 528 + (uint32_t)seg * 16,
             w2p + (size_t)row * 2048 + chunk * 256 + seg * 8);
    }
}

__global__ void __launch_bounds__(256, 2)
ffn_mma_kernel(int layer, const float* __restrict__ b2,
               const float* __restrict__ lng, const float* __restrict__ lnb,
               const float* __restrict__ fc1w, const float* __restrict__ fc1b,
               const float* __restrict__ fc2w, const float* __restrict__ fc2b,
               float* __restrict__ out) {
    extern __shared__ char smc[];
    const int t = threadIdx.x, lane = t & 31, warp = t >> 5;
    const int g = lane >> 2, tg = lane & 3;
    const int rw = warp & 1, jq = warp >> 1;
    const uint32_t sbase = (uint32_t)__cvta_generic_to_shared(smc);
    const int rbase = blockIdx.x * 32 + rw * 16;

    const int lm = lane >> 3, lr = lane & 7;
    const uint32_t okh = (uint32_t)((((lm >> 1) * 8 + lr) * 16) + (lm & 1) * 4096);
    const uint32_t ovh = (uint32_t)(lr * 528 + (lm & 1) * 16 + (lm >> 1) * 4224);

    uint32_t qhi[4], qlo[4];
    {
        int r0 = rbase + g, r1 = r0 + 8;
        float v0a = g_h[r0 * DM + 2 * tg],     v1a = g_h[r0 * DM + 2 * tg + 1];
        float v0b = g_h[r1 * DM + 2 * tg],     v1b = g_h[r1 * DM + 2 * tg + 1];
        float v2a, v3a, v2b, v3b;
        if (tg < 3) {
            v2a = g_h[r0 * DM + 8 + 2 * tg]; v3a = g_h[r0 * DM + 9 + 2 * tg];
            v2b = g_h[r1 * DM + 8 + 2 * tg]; v3b = g_h[r1 * DM + 9 + 2 * tg];
        } else {
            v2a = 1.0f; v3a = 0.f;
            v2b = 1.0f; v3b = 0.f;
        }
        float vals[4][2] = {{v0a, v1a}, {v0b, v1b}, {v2a, v3a}, {v2b, v3b}};
#pragma unroll
        for (int i = 0; i < 4; i++) {
            qhi[i] = h2pack(vals[i][0], vals[i][1]);
            __half2 hh = *(__half2*)&qhi[i];
            qlo[i] = h2pack(vals[i][0] - __low2float(hh), vals[i][1] - __high2float(hh));
        }
    }

    float O0[4] = {0.f, 0.f, 0.f, 0.f};
    float O1[4] = {0.f, 0.f, 0.f, 0.f};

    ffn_cp(sbase, 0, 0, t, layer);
    CP_COMMIT();

    for (int c = 0; c < 8; c++) {
        if (c < 7) {
            ffn_cp(sbase, (c + 1) & 1, c + 1, t, layer);
            CP_COMMIT();
            CP_WAIT(1);
        } else {
            CP_WAIT(0);
        }
        __syncthreads();

        uint32_t kaddr = sbase + (uint32_t)(c & 1) * FBUF + okh + (uint32_t)jq * 1024;
        uint32_t vaddr = sbase + (uint32_t)(c & 1) * FBUF + FW1B + ovh + (uint32_t)jq * 128;

#pragma unroll
        for (int step = 0; step < 4; step++) {
            uint32_t kh[4], kl[4], vh[4], vl[4];
            ldsm4(kh, kaddr);
            ldsm4(kl, kaddr + 8192);
            ldsm4(vh, vaddr);
            ldsm4(vl, vaddr + 8448);
            kaddr += 256;
            vaddr += 32;

            float S0[4] = {0.f, 0.f, 0.f, 0.f}, S1[4] = {0.f, 0.f, 0.f, 0.f};
            mma16816(S0, qhi, kh,     S0);
            mma16816(S0, qhi, kl,     S0);
            mma16816(S0, qlo, kh,     S0);
            mma16816(S1, qhi, kh + 2, S1);
            mma16816(S1, qhi, kl + 2, S1);
            mma16816(S1, qlo, kh + 2, S1);

            float p[8];
#pragma unroll
            for (int i = 0; i < 4; i++) { p[i] = fmaxf(S0[i], 0.f); p[4 + i] = fmaxf(S1[i], 0.f); }
            uint32_t phi[4], plo[4];
#pragma unroll
            for (int i = 0; i < 4; i++) {
                phi[i] = h2pack(p[2 * i], p[2 * i + 1]);
                __half2 hh = *(__half2*)&phi[i];
                plo[i] = h2pack(p[2 * i] - __low2float(hh), p[2 * i + 1] - __high2float(hh));
            }

            mma16816(O0, phi, vh,     O0);
            mma16816(O1, phi, vh + 2, O1);
            mma16816(O0, plo, vh,     O0);
            mma16816(O1, plo, vh + 2, O1);
            mma16816(O0, phi, vl,     O0);
            mma16816(O1, phi, vl + 2, O1);
        }
        __syncthreads();
    }

    {
        float* osum = (float*)smc;
        int lrw = rw * 16 + g;
        float* om = osum + jq * 512;
        om[lrw * 16 + 2 * tg]           = O0[0];
        om[lrw * 16 + 2 * tg + 1]       = O0[1];
        om[lrw * 16 + 8 + 2 * tg]       = O1[0];
        om[lrw * 16 + 9 + 2 * tg]       = O1[1];
        om[(lrw + 8) * 16 + 2 * tg]     = O0[2];
        om[(lrw + 8) * 16 + 2 * tg + 1] = O0[3];
        om[(lrw + 8) * 16 + 8 + 2 * tg] = O1[2];
        om[(lrw + 8) * 16 + 9 + 2 * tg] = O1[3];
        __syncthreads();
        if (t < 32) {
            int row = blockIdx.x * 32 + t;
            float pre[14], mu = 0.f;
#pragma unroll
            for (int d = 0; d < 14; d++) {
                float v = osum[t * 16 + d] + osum[512 + t * 16 + d]
                        + osum[1024 + t * 16 + d] + osum[1536 + t * 16 + d]
                        + __ldg(b2 + d) + g_h[row * DM + d];
                pre[d] = v; mu += v;
            }
            mu *= (1.f / 14.f);
            float var = 0.f;
#pragma unroll
            for (int d = 0; d < 14; d++) { float z = pre[d] - mu; var = fmaf(z, z, var); }
            float rs = rsqrtf(var * (1.f / 14.f) + EPS);
            float hv[14];
#pragma unroll
            for (int d = 0; d < 14; d++) {
                hv[d] = (pre[d] - mu) * rs * __ldg(lng + d) + __ldg(lnb + d);
                g_h[row * DM + d] = hv[d];
            }
            if (layer == 1) {
                float size = __ldg(fc2b);
#pragma unroll
                for (int d2 = 0; d2 < 14; d2++) {
                    float s = __ldg(fc1b + d2);
#pragma unroll
                    for (int d = 0; d < 14; d++) s = fmaf(hv[d], __ldg(fc1w + d2 * 14 + d), s);
                    size = fmaf(s, __ldg(fc2w + d2), size);
                }
                out[row] = size;
                g_sizef[row] = (float)(int)size;
            }
        }
    }
}

// ---------------- head2 via mma.sync ----------------
#define H2WB 16384
#define H2_INS   (2 * H2WB)
#define H2_R1H   (H2_INS + 1632 * 4)
#define H2_R1L   (H2_R1H + 32 * 264 * 2)
#define H2_RED   (H2_R1L + 32 * 264 * 2)
#define H2_SMEM  (H2_RED + 128 * 4)
__device__ __forceinline__ void h2cp(uint32_t sbase, int buf, int kstep, int t) {
    uint32_t dst = sbase + (uint32_t)buf * H2WB;
    const __half* src = g_w4p + (size_t)kstep * 8192;
#pragma unroll
    for (int s = 0; s < 4; s++) {
        int i = t + s * 256;
        cp16(dst + (uint32_t)i * 16, src + (size_t)i * 8);
    }
}

__global__ void __launch_bounds__(256, 2)
head2_mma_kernel(const float* __restrict__ x, const float* __restrict__ y,
                 const float* __restrict__ w3, const float* __restrict__ b3,
                 const float* __restrict__ b4,
                 const float* __restrict__ w5, const float* __restrict__ b5,
                 float* __restrict__ out) {
    extern __shared__ char smc[];
    float*  ins = (float*)(smc + H2_INS);
    __half* r1h = (__half*)(smc + H2_R1H);
    __half* r1l = (__half*)(smc + H2_R1L);
    float*  red = (float*)(smc + H2_RED);
    const int t = threadIdx.x, lane = t & 31, warp = t >> 5;
    const int g = lane >> 2, tg = lane & 3;
    const int rw = warp & 1, nq = warp >> 1;
    const uint32_t sbase = (uint32_t)__cvta_generic_to_shared(smc);
    const int rbase = blockIdx.x * 32;

    h2cp(sbase, 0, 0, t);
    CP_COMMIT();
    h2cp(sbase, 1, 1, t);
    CP_COMMIT();

    for (int i = t; i < 32 * 51; i += 256) {
        int r = i / 51, c = i % 51, row = rbase + r;
        float v;
        if (c == 0)      v = g_sizef[row];
        else if (c < 15) v = x[row * DM + c - 1];
        else             v = y[row * MF + c - 15];
        ins[i] = v;
    }
    __syncthreads();

    {
        float r1a[32];
        float b3t = __ldg(b3 + t);
#pragma unroll
        for (int r = 0; r < 32; r++) r1a[r] = b3t;
        const float* w3r = w3 + t * 51;
        for (int i = 0; i < 51; i++) {
            float w = __ldg(w3r + i);
#pragma unroll
            for (int r = 0; r < 32; r++) r1a[r] = fmaf(ins[r * 51 + i], w, r1a[r]);
        }
#pragma unroll
        for (int r = 0; r < 32; r++) {
            float v = fmaxf(r1a[r], 0.f);
            __half h = __float2half_rn(v);
            r1h[r * 264 + t] = h;
            r1l[r * 264 + t] = __float2half_rn(v - __half2float(h));
        }
    }
    __syncthreads();

    float O[8][4];
#pragma unroll
    for (int nt = 0; nt < 8; nt++)
#pragma unroll
        for (int i = 0; i < 4; i++) O[nt][i] = 0.f;

    const int r0 = rw * 16 + g;
    for (int kstep = 0; kstep < 16; kstep++) {
        CP_WAIT(1);
        __syncthreads();

        const int kb2 = kstep * 16 + 2 * tg;
        uint32_t ahi[4], alo[4];
        ahi[0] = *(const uint32_t*)&r1h[r0 * 264 + kb2];
        ahi[1] = *(const uint32_t*)&r1h[(r0 + 8) * 264 + kb2];
        ahi[2] = *(const uint32_t*)&r1h[r0 * 264 + kb2 + 8];
        ahi[3] = *(const uint32_t*)&r1h[(r0 + 8) * 264 + kb2 + 8];
        alo[0] = *(const uint32_t*)&r1l[r0 * 264 + kb2];
        alo[1] = *(const uint32_t*)&r1l[(r0 + 8) * 264 + kb2];
        alo[2] = *(const uint32_t*)&r1l[r0 * 264 + kb2 + 8];
        alo[3] = *(const uint32_t*)&r1l[(r0 + 8) * 264 + kb2 + 8];

        const char* wb = smc + (kstep & 1) * H2WB;
#pragma unroll
        for (int nt = 0; nt < 8; nt++) {
            int o0 = nq * 64 + nt * 8;
            const char* p = wb + (size_t)(o0 + g) * 16 + tg * 4;
            uint32_t bh[2] = { *(const uint32_t*)p,          *(const uint32_t*)(p + 4096) };
            uint32_t bl[2] = { *(const uint32_t*)(p + 8192), *(const uint32_t*)(p + 12288) };
            mma16816(O[nt], ahi, bh, O[nt]);
            mma16816(O[nt], ahi, bl, O[nt]);
            mma16816(O[nt], alo, bh, O[nt]);
        }
        __syncthreads();
        if (kstep + 2 < 16) {
            h2cp(sbase, kstep & 1, kstep + 2, t);
            CP_COMMIT();
        }
    }

    float s0 = 0.f, s1 = 0.f;
#pragma unroll
    for (int nt = 0; nt < 8; nt++) {
        int o = nq * 64 + nt * 8 + 2 * tg;
        float b4a = __ldg(b4 + o),     b4b = __ldg(b4 + o + 1);
        float w5a = __ldg(w5 + o),     w5b = __ldg(w5 + o + 1);
        s0 += fmaxf(O[nt][0] + b4a, 0.f) * w5a + fmaxf(O[nt][1] + b4b, 0.f) * w5b;
        s1 += fmaxf(O[nt][2] + b4a, 0.f) * w5a + fmaxf(O[nt][3] + b4b, 0.f) * w5b;
    }
    s0 += __shfl_xor_sync(0xffffffffu, s0, 1); s0 += __shfl_xor_sync(0xffffffffu, s0, 2);
    s1 += __shfl_xor_sync(0xffffffffu, s1, 1); s1 += __shfl_xor_sync(0xffffffffu, s1, 2);
    if (tg == 0) {
        red[nq * 32 + r0] = s0;
        red[nq * 32 + r0 + 8] = s1;
    }
    __syncthreads();
    if (t < 32) {
        int row = rbase + t;
        float s = __ldg(b5) + red[t] + red[32 + t] + red[64 + t] + red[96 + t];
        out[NROWS + row] = (g_sizef[row] != 0.f) ? s : 0.f;
    }
}

// ---------------- launcher ----------------
extern "C" void kernel_launch(void* const* d_in, const int* in_sizes, int n_in,
                              void* d_out, int out_size) {
    const float* x    = (const float*)d_in[0];
    const float* y    = (const float*)d_in[1];
    const float* wqkv = (const float*)d_in[2];
    const float* bqkv = (const float*)d_in[3];
    const float* wo   = (const float*)d_in[4];
    const float* bo   = (const float*)d_in[5];
    const float* ln1g = (const float*)d_in[6];
    const float* ln1b = (const float*)d_in[7];
    const float* ffw1 = (const float*)d_in[8];
    const float* ffb1 = (const float*)d_in[9];
    const float* ffw2 = (const float*)d_in[10];
    const float* ffb2 = (const float*)d_in[11];
    const float* ln2g = (const float*)d_in[12];
    const float* ln2b = (const float*)d_in[13];
    const float* fc1w = (const float*)d_in[14];
    const float* fc1b = (const float*)d_in[15];
    const float* fc2w = (const float*)d_in[16];
    const float* fc2b = (const float*)d_in[17];
    const float* fc3w = (const float*)d_in[18];
    const float* fc3b = (const float*)d_in[19];
    const float* fc4w = (const float*)d_in[20];
    const float* fc4b = (const float*)d_in[21];
    const float* fc5w = (const float*)d_in[22];
    const float* fc5b = (const float*)d_in[23];
    float* out = (float*)d_out;

    cudaFuncSetAttribute(attn_mma_kernel,  cudaFuncAttributeMaxDynamicSharedMemorySize, ATTN_SMEM);
    cudaFuncSetAttribute(ffn_mma_kernel,   cudaFuncAttributeMaxDynamicSharedMemorySize, FFN_SMEM);
    cudaFuncSetAttribute(head2_mma_kernel, cudaFuncAttributeMaxDynamicSharedMemorySize, H2_SMEM);

    wprep_all_kernel<<<16, 256>>>(ffw1, ffb1, ffw2);
    wprep4_kernel<<<16, 256>>>(fc4w);
    for (int l = 0; l < 2; l++) {
        qkv_prep_kernel<<<128, 256>>>(x, (l == 0) ? 1 : 0, wqkv + l * 588, bqkv + l * 42);
        attn_mma_kernel<<<64 * NPART, 256, ATTN_SMEM>>>();
        combine_kernel<<<256, 256>>>(x, (l == 0) ? 1 : 0, wo + l * 196, bo + l * 14,
                                     ln1g + l * 14, ln1b + l * 14);
        ffn_mma_kernel<<<256, 256, FFN_SMEM>>>(l, ffb2 + l * 14, ln2g + l * 14, ln2b + l * 14,
                                               fc1w, fc1b, fc2w, fc2b, out);
    }
    head2_mma_kernel<<<256, 256, H2_SMEM>>>(x, y, fc3w, fc3b, fc4b, fc5w, fc5b, out);
}